// round 13
// baseline (speedup 1.0000x reference)
#include <cuda_runtime.h>
#include <cuda_bf16.h>
#include <cstdint>
#include <cstddef>

#define N0 1048576
#define N1 131072
#define N2 16384
#define E0 1048576
#define E1 131072
#define EP 16384
#define D  128

// ---------------- scratch (device globals; no allocation) ----------------
__device__ float g_m[(size_t)N1 * D];
__device__ float g_ws[N1];
__device__ float g_h1[(size_t)N1 * D];
__device__ float g_hitem[(size_t)N2 * D];
__device__ float g_bias[N2];
__device__ uint8_t g_wimg[393216];

#define IMG_Q0 0
#define IMG_W0 65536
#define IMG_Q1 196608
#define IMG_W1 262144

// ---------------- helpers ----------------
__device__ __forceinline__ uint32_t smem_u32(const void* p) {
    uint32_t a;
    asm("{ .reg .u64 t; cvta.to.shared.u64 t, %1; cvt.u32.u64 %0, t; }" : "=r"(a) : "l"(p));
    return a;
}

__device__ __forceinline__ void ldsm4(uint32_t* r, uint32_t addr) {
    asm volatile("ldmatrix.sync.aligned.m8n8.x4.shared.b16 {%0,%1,%2,%3}, [%4];"
                 : "=r"(r[0]), "=r"(r[1]), "=r"(r[2]), "=r"(r[3]) : "r"(addr));
}

__device__ __forceinline__ void mma16816(float* c, const uint32_t* a, const uint32_t* b) {
    asm volatile("mma.sync.aligned.m16n8k16.row.col.f32.bf16.bf16.f32 "
                 "{%0,%1,%2,%3}, {%4,%5,%6,%7}, {%8,%9}, {%0,%1,%2,%3};"
                 : "+f"(c[0]), "+f"(c[1]), "+f"(c[2]), "+f"(c[3])
                 : "r"(a[0]), "r"(a[1]), "r"(a[2]), "r"(a[3]), "r"(b[0]), "r"(b[1]));
}

__device__ __forceinline__ void split2(float a, float b, uint32_t& hi, uint32_t& lo) {
    __nv_bfloat16 ha = __float2bfloat16(a), hb = __float2bfloat16(b);
    float ra = a - __bfloat162float(ha), rb = b - __bfloat162float(hb);
    __nv_bfloat16 la = __float2bfloat16(ra), lb = __float2bfloat16(rb);
    hi = (uint32_t)__bfloat16_as_ushort(ha) | ((uint32_t)__bfloat16_as_ushort(hb) << 16);
    lo = (uint32_t)__bfloat16_as_ushort(la) | ((uint32_t)__bfloat16_as_ushort(lb) << 16);
}

// swizzled byte offset within a (rows x 128)-bf16 tile (pitch 256B):
__device__ __forceinline__ uint32_t tswz(int r, int cbyte) {
    return (uint32_t)r * 256u + ((uint32_t)cbyte ^ (((uint32_t)r & 7u) << 4));
}

// ---------------- weight image prep (all 4 weights in one launch) ----------
__device__ __forceinline__ void prep_one(const float* __restrict__ W, int Kw,
                                         uint8_t* __restrict__ img, int gid, int gsz) {
    int total = Kw * 128;
    for (int f = gid; f < total; f += gsz) {
        int k = f >> 7, n = f & 127;
        int c = k >> 7, kk = k & 127;
        float x = W[f];
        __nv_bfloat16 h = __float2bfloat16(x);
        float r = x - __bfloat162float(h);
        __nv_bfloat16 l = __float2bfloat16(r);
        size_t base = (size_t)c * 65536 + tswz(n, kk * 2);
        *(__nv_bfloat16*)(img + base) = h;
        *(__nv_bfloat16*)(img + base + 32768) = l;
    }
}

__global__ void prep_weight_all(const float* __restrict__ Q0, const float* __restrict__ W0,
                                const float* __restrict__ Q1, const float* __restrict__ W1,
                                uint8_t* __restrict__ img) {
    int gid = blockIdx.x * blockDim.x + threadIdx.x;
    int gsz = gridDim.x * blockDim.x;
    prep_one(Q0, 128, img + IMG_Q0, gid, gsz);
    prep_one(W0, 256, img + IMG_W0, gid, gsz);
    prep_one(Q1, 128, img + IMG_Q1, gid, gsz);
    prep_one(W1, 256, img + IMG_W1, gid, gsz);
}

// ---------------- zero ----------------
__global__ void zero_kernel(float4* __restrict__ p, int n4) {
    int i = blockIdx.x * blockDim.x + threadIdx.x;
    if (i < n4) p[i] = make_float4(0.f, 0.f, 0.f, 0.f);
}

// ---------------- core MMA over one 128-K chunk ----------------
// warp tile (MT*16) x (NP*16). acc = float[MT*NP*2][4].
template <int MT, int NP>
__device__ __forceinline__ void mma_K128(float* acc, uint32_t Ah, uint32_t Al,
                                         uint32_t Bh, uint32_t Bl, int lane,
                                         int mb, int nb)
{
    const uint32_t sw = (uint32_t)(lane & 7) << 4;
    const uint32_t arow = (uint32_t)(((lane >> 3) & 1) * 8 + (lane & 7));
    const uint32_t akh = (uint32_t)((lane >> 4) * 16);
    const uint32_t brow = (uint32_t)(((lane >> 4) & 1) * 8 + (lane & 7));
    const uint32_t bkh = (uint32_t)(((lane >> 3) & 1) * 16);

#pragma unroll
    for (int ks = 0; ks < 8; ks++) {
        uint32_t ako = ((uint32_t)(32 * ks) + akh) ^ sw;
        uint32_t bko = ((uint32_t)(32 * ks) + bkh) ^ sw;
        uint32_t ah[MT][4], al[MT][4];
#pragma unroll
        for (int mt = 0; mt < MT; mt++) {
            uint32_t ro = (uint32_t)(mb + mt * 16) * 256u + arow * 256u;
            ldsm4(ah[mt], Ah + ro + ako);
            ldsm4(al[mt], Al + ro + ako);
        }
#pragma unroll
        for (int np = 0; np < NP; np++) {
            uint32_t no = (uint32_t)(nb + np * 16) * 256u + brow * 256u;
            uint32_t bh[4], bl[4];
            ldsm4(bh, Bh + no + bko);
            ldsm4(bl, Bl + no + bko);
#pragma unroll
            for (int mt = 0; mt < MT; mt++)
#pragma unroll
                for (int nt = 0; nt < 2; nt++) {
                    float* c = acc + (mt * NP * 2 + np * 2 + nt) * 4;
                    mma16816(c, ah[mt], bh + nt * 2);
                    mma16816(c, ah[mt], bl + nt * 2);
                    mma16816(c, al[mt], bh + nt * 2);
                }
        }
    }
}

// ====== PERSISTENT fused gemm+scatter (M-tile 64, 256 thr / 8 warps,
//        2 CTAs/SM), warp tile 32x32, index prefetch, v4 paired scatter =====
// smem: bias 512 @0, wbuf 256 @512, dbuf 256 @768, A_hi @1024 (16K),
//       A_lo @17408 (16K), B @33792 (64K) -> total 99328
__global__ __launch_bounds__(256, 2) void gemm_scatter(
    const float* __restrict__ X, const int* __restrict__ nids,
    const int* __restrict__ srcE, const int* __restrict__ dstE,
    const float* __restrict__ wE,
    const uint8_t* __restrict__ bimg, const float* __restrict__ b,
    float* __restrict__ m, float* __restrict__ ws, int numTiles)
{
    extern __shared__ uint8_t sm[];
    const uint32_t sb = smem_u32(sm);
    const int tid = threadIdx.x, wid = tid >> 5, lane = tid & 31;
    const uint32_t A1 = 1024, A2 = 17408, B1 = 33792;
    float* bsp  = (float*)sm;
    float* wbuf = (float*)(sm + 512);
    int*   dbuf = (int*)(sm + 768);
    const int G = gridDim.x;

    if (tid < 32) ((float4*)bsp)[tid] = ((const float4*)b)[tid];
    for (int i = tid; i < 4096; i += 256)
        ((float4*)(sm + B1))[i] = ((const float4*)bimg)[i];

    const int mb = (wid >> 2) * 32, nb = (wid & 3) * 32;

    // prefetch resolved row indices for first tile
    int srN[8];
    if (blockIdx.x < numTiles) {
        const int row0 = blockIdx.x * 64;
#pragma unroll
        for (int i = 0; i < 8; i++) {
            int e = srcE[row0 + wid + 8 * i];
            srN[i] = nids ? nids[e] : e;
        }
    }

    for (int t = blockIdx.x; t < numTiles; t += G) {
        const int row0 = t * 64;
        if (tid < 64) {
            wbuf[tid] = wE[row0 + tid];
            dbuf[tid] = dstE[row0 + tid];
        }
        // gather + split A using prefetched indices: rows wid+8i, col lane
#pragma unroll
        for (int i = 0; i < 8; i++) {
            int r = wid + 8 * i;
            float4 v = ((const float4*)(X + (size_t)srN[i] * 128))[lane];
            uint32_t off = tswz(r, lane * 8);
            uint2 hi, lo;
            split2(v.x, v.y, hi.x, lo.x);
            split2(v.z, v.w, hi.y, lo.y);
            *(uint2*)(sm + A1 + off) = hi;
            *(uint2*)(sm + A2 + off) = lo;
        }
        __syncthreads();

        // prefetch indices for next tile (covered by MMA below)
        const int tn = t + G;
        if (tn < numTiles) {
            const int rown = tn * 64;
#pragma unroll
            for (int i = 0; i < 8; i++) {
                int e = srcE[rown + wid + 8 * i];
                srN[i] = nids ? nids[e] : e;
            }
        }

        float acc[32];
#pragma unroll
        for (int i = 0; i < 32; i++) acc[i] = 0.f;
        mma_K128<2, 2>(acc, sb + A1, sb + A2, sb + B1, sb + B1 + 32768, lane, mb, nb);

        // scatter: lanes q and q^1 share the output row; pair values via
        // shfl.xor and issue ONE red.v4 per 4 contiguous cols (even lanes)
#pragma unroll
        for (int mt = 0; mt < 2; mt++)
#pragma unroll
            for (int h = 0; h < 2; h++) {
                int el = mb + mt * 16 + (lane >> 2) + h * 8;
                int d  = dbuf[el];
                float wt = wbuf[el];
                float* rowp = m + (size_t)d * 128;
#pragma unroll
                for (int g = 0; g < 4; g++) {
                    int c0 = nb + g * 8 + 2 * (lane & 3);
                    float* a4 = acc + (mt * 4 + g) * 4 + h * 2;
                    float v0 = fmaxf(a4[0] + bsp[c0], 0.f) * wt;
                    float v1 = fmaxf(a4[1] + bsp[c0 + 1], 0.f) * wt;
                    float p0 = __shfl_xor_sync(0xffffffffu, v0, 1);
                    float p1 = __shfl_xor_sync(0xffffffffu, v1, 1);
                    if ((lane & 1) == 0) {
                        asm volatile("red.global.add.v4.f32 [%0], {%1, %2, %3, %4};"
                                     :: "l"(rowp + c0), "f"(v0), "f"(v1),
                                        "f"(p0), "f"(p1) : "memory");
                    }
                }
            }
        if (tid < 64) atomicAdd(ws + dbuf[tid], wbuf[tid]);
        __syncthreads();
    }
}

// ======== PERSISTENT zconv (M-tile 128, 512 thr / 16 warps, 1 CTA/SM) ===
//   warp tile 32x32 (mg4 x ng4). B fully resident (128K).
// smem: bias 512 @0, ssb 2K @512, A_hi @2560 (32K), A_lo @35328 (32K),
//       B @68096 (128K) -> total 199168
__global__ __launch_bounds__(512, 1) void zconv_mma(
    const float* __restrict__ gm, const float* __restrict__ gws,
    const float* __restrict__ Xd, const int* __restrict__ idxd,
    const uint8_t* __restrict__ bimg, const float* __restrict__ b,
    const float* __restrict__ addX, const int* __restrict__ addIdx,
    const float* __restrict__ biasv, float* __restrict__ bias_out,
    float* __restrict__ out, int numTiles)
{
    extern __shared__ uint8_t sm[];
    const uint32_t sb = smem_u32(sm);
    const int tid = threadIdx.x, wid = tid >> 5, lane = tid & 31;
    const uint32_t A1 = 2560, A2 = 35328, B1 = 68096;
    float* bsp = (float*)sm;
    float* ssb = (float*)(sm + 512);

    if (tid < 32) ((float4*)bsp)[tid] = ((const float4*)b)[tid];
    for (int i = tid; i < 8192; i += 512)
        ((float4*)(sm + B1))[i] = ((const float4*)bimg)[i];

    const int mb = (wid >> 2) * 32, nb = (wid & 3) * 32;
    const int wn = wid & 3;

    for (int t = blockIdx.x; t < numTiles; t += gridDim.x) {
        const int row0 = t * 128;
        float acc[32];
#pragma unroll
        for (int i = 0; i < 32; i++) acc[i] = 0.f;

#pragma unroll
        for (int c = 0; c < 2; c++) {
#pragma unroll
            for (int i = 0; i < 8; i++) {
                int f = tid + 512 * i;
                int r = f >> 5, q = f & 31;
                int row = row0 + r;
                float4 v;
                if (c == 0) {
                    float inv = 1.f / fmaxf(gws[row], 1.f);
                    v = ((const float4*)(gm + (size_t)row * 128))[q];
                    v.x *= inv; v.y *= inv; v.z *= inv; v.w *= inv;
                } else {
                    size_t sr = idxd ? (size_t)idxd[row] : (size_t)row;
                    v = ((const float4*)(Xd + sr * 128))[q];
                }
                uint32_t off = tswz(r, q * 8);
                uint2 hi, lo;
                split2(v.x, v.y, hi.x, lo.x);
                split2(v.z, v.w, hi.y, lo.y);
                *(uint2*)(sm + A1 + off) = hi;
                *(uint2*)(sm + A2 + off) = lo;
            }
            __syncthreads();
            uint32_t Bc = sb + B1 + (uint32_t)c * 65536;
            mma_K128<2, 2>(acc, sb + A1, sb + A2, Bc, Bc + 32768, lane, mb, nb);
            __syncthreads();
        }

        float ss[2][2] = {{0.f, 0.f}, {0.f, 0.f}};
#pragma unroll
        for (int mt = 0; mt < 2; mt++)
#pragma unroll
            for (int g = 0; g < 4; g++) {
                int c0 = nb + g * 8 + 2 * (lane & 3);
                float* a4 = acc + (mt * 4 + g) * 4;
                a4[0] = fmaxf(a4[0] + bsp[c0], 0.f);
                a4[1] = fmaxf(a4[1] + bsp[c0 + 1], 0.f);
                a4[2] = fmaxf(a4[2] + bsp[c0], 0.f);
                a4[3] = fmaxf(a4[3] + bsp[c0 + 1], 0.f);
                ss[mt][0] += a4[0] * a4[0] + a4[1] * a4[1];
                ss[mt][1] += a4[2] * a4[2] + a4[3] * a4[3];
            }
#pragma unroll
        for (int mt = 0; mt < 2; mt++)
#pragma unroll
            for (int h = 0; h < 2; h++) {
                float v = ss[mt][h];
                v += __shfl_xor_sync(0xffffffffu, v, 1);
                v += __shfl_xor_sync(0xffffffffu, v, 2);
                ss[mt][h] = v;
            }
        if ((lane & 3) == 0) {
#pragma unroll
            for (int mt = 0; mt < 2; mt++)
#pragma unroll
                for (int h = 0; h < 2; h++) {
                    int rl = mb + mt * 16 + (lane >> 2) + h * 8;
                    ssb[rl * 4 + wn] = ss[mt][h];
                }
        }
        __syncthreads();

#pragma unroll
        for (int mt = 0; mt < 2; mt++)
#pragma unroll
            for (int h = 0; h < 2; h++) {
                int rl = mb + mt * 16 + (lane >> 2) + h * 8;
                int rg = row0 + rl;
                float tsum = ssb[rl * 4] + ssb[rl * 4 + 1] + ssb[rl * 4 + 2] + ssb[rl * 4 + 3];
                float sc = (tsum > 0.f) ? rsqrtf(tsum) : 1.f;
                int ai = 0;
                if (addIdx) {
                    ai = addIdx[rg];
                    if ((lane & 3) == 0 && wn == 0) bias_out[rg] = biasv[ai];
                }
#pragma unroll
                for (int g = 0; g < 4; g++) {
                    int c0 = nb + g * 8 + 2 * (lane & 3);
                    float* a4 = acc + (mt * 4 + g) * 4 + h * 2;
                    float2 o;
                    o.x = a4[0] * sc;
                    o.y = a4[1] * sc;
                    if (addIdx) {
                        float2 av = *(const float2*)(addX + (size_t)ai * 128 + c0);
                        o.x += av.x; o.y += av.y;
                    }
                    *(float2*)(out + (size_t)rg * 128 + c0) = o;
                }
            }
        __syncthreads();
    }
}

// ---------------- pair scores ----------------
__global__ __launch_bounds__(256) void score_kernel(
    const float* __restrict__ h, const float* __restrict__ bn,
    const int* __restrict__ ps, const int* __restrict__ pd,
    const int* __restrict__ ns, const int* __restrict__ nd,
    float* __restrict__ out)
{
    int e = (blockIdx.x * blockDim.x + threadIdx.x) >> 5;
    if (e >= EP) return;
    int lane = threadIdx.x & 31;
    int a = ps[e], b2 = pd[e], c = ns[e], d2 = nd[e];

    float4 u, v;
    u = ((const float4*)(h + (size_t)a * 128))[lane];
    v = ((const float4*)(h + (size_t)b2 * 128))[lane];
    float sp = u.x * v.x + u.y * v.y + u.z * v.z + u.w * v.w;
    u = ((const float4*)(h + (size_t)c * 128))[lane];
    v = ((const float4*)(h + (size_t)d2 * 128))[lane];
    float sn = u.x * v.x + u.y * v.y + u.z * v.z + u.w * v.w;
#pragma unroll
    for (int o = 16; o; o >>= 1) {
        sp += __shfl_xor_sync(0xffffffffu, sp, o);
        sn += __shfl_xor_sync(0xffffffffu, sn, o);
    }
    if (lane == 0) {
        float pos = sp + bn[a] + bn[b2];
        float neg = sn + bn[c] + bn[d2];
        out[e] = fmaxf(neg - pos + 1.0f, 0.f);
    }
}

// ---------------- launch ----------------
extern "C" void kernel_launch(void* const* d_in, const int* in_sizes, int n_in,
                              void* d_out, int out_size)
{
    const float* emb  = (const float*)d_in[0];
    const float* bias = (const float*)d_in[1];
    const int*   nids = (const int*)d_in[2];
    const int*   src0 = (const int*)d_in[3];
    const int*   dst0 = (const int*)d_in[4];
    const float* w0   = (const float*)d_in[5];
    const int*   src1 = (const int*)d_in[6];
    const int*   dst1 = (const int*)d_in[7];
    const float* w1   = (const float*)d_in[8];
    const int*   pos_src = (const int*)d_in[9];
    const int*   pos_dst = (const int*)d_in[10];
    const int*   neg_src = (const int*)d_in[11];
    const int*   neg_dst = (const int*)d_in[12];
    const float* Q0w = (const float*)d_in[13];
    const float* Q0b = (const float*)d_in[14];
    const float* W0w = (const float*)d_in[15];
    const float* W0b = (const float*)d_in[16];
    const float* Q1w = (const float*)d_in[17];
    const float* Q1b = (const float*)d_in[18];
    const float* W1w = (const float*)d_in[19];
    const float* W1b = (const float*)d_in[20];
    float* out = (float*)d_out;

    float *p_m, *p_ws, *p_h1, *p_hi, *p_b;
    uint8_t* p_img;
    cudaGetSymbolAddress((void**)&p_m,  g_m);
    cudaGetSymbolAddress((void**)&p_ws, g_ws);
    cudaGetSymbolAddress((void**)&p_h1, g_h1);
    cudaGetSymbolAddress((void**)&p_hi, g_hitem);
    cudaGetSymbolAddress((void**)&p_b,  g_bias);
    cudaGetSymbolAddress((void**)&p_img, g_wimg);

    const int SMEM_G = 1024 + 2 * 16384 + 65536;            // 99328
    const int SMEM_Z = 2560 + 2 * 32768 + 2 * 65536;        // 199168
    cudaFuncSetAttribute(gemm_scatter, cudaFuncAttributeMaxDynamicSharedMemorySize, SMEM_G);
    cudaFuncSetAttribute(zconv_mma,    cudaFuncAttributeMaxDynamicSharedMemorySize, SMEM_Z);

    prep_weight_all<<<128, 256>>>(Q0w, W0w, Q1w, W1w, p_img);

    const int GS_GRID = 296;
    const int ZC_GRID = 148;

    // layer 0: fused n = relu(emb[nids[src0]] @ Q0 + b0); scatter into m, ws
    zero_kernel<<<(N1 * 32 + 255) / 256, 256>>>((float4*)p_m, N1 * 32);
    zero_kernel<<<(N1 / 4 + 255) / 256, 256>>>((float4*)p_ws, N1 / 4);
    gemm_scatter<<<GS_GRID, 256, SMEM_G>>>(emb, nids, src0, dst0, w0,
                                           p_img + IMG_Q0, Q0b, p_m, p_ws, E0 / 64);

    // h1 = normalize(relu(concat(m/ws, emb[nids]) @ W0 + b0))
    zconv_mma<<<ZC_GRID, 512, SMEM_Z>>>(p_m, p_ws, emb, nids, p_img + IMG_W0, W0b,
                                        nullptr, nullptr, nullptr, nullptr, p_h1,
                                        N1 / 128);

    // layer 1: fused n1 = relu(h1[src1] @ Q1 + b1); scatter into m, ws
    zero_kernel<<<(N2 * 32 + 255) / 256, 256>>>((float4*)p_m, N2 * 32);
    zero_kernel<<<(N2 / 4 + 255) / 256, 256>>>((float4*)p_ws, N2 / 4);
    gemm_scatter<<<GS_GRID, 256, SMEM_G>>>(p_h1, nullptr, src1, dst1, w1,
                                           p_img + IMG_Q1, Q1b, p_m, p_ws, E1 / 64);

    // h_item = emb[nids[:N2]] + normalize(relu(concat(m/ws, h1) @ W1 + b1))
    zconv_mma<<<128, 512, SMEM_Z>>>(p_m, p_ws, p_h1, nullptr, p_img + IMG_W1, W1b,
                                    emb, nids, bias, p_b, p_hi, N2 / 128);

    score_kernel<<<(EP * 32) / 256, 256>>>(p_hi, p_b, pos_src, pos_dst,
                                           neg_src, neg_dst, out);
}

// round 14
// speedup vs baseline: 1.1865x; 1.1865x over previous
#include <cuda_runtime.h>
#include <cuda_bf16.h>
#include <cuda_fp16.h>
#include <cstdint>
#include <cstddef>

#define N0 1048576
#define N1 131072
#define N2 16384
#define E0 1048576
#define E1 131072
#define EP 16384
#define D  128

// ---------------- scratch (device globals; no allocation) ----------------
__device__ float g_m[(size_t)N1 * D];
__device__ float g_ws[N1];
__device__ float g_h1[(size_t)N1 * D];
__device__ float g_hitem[(size_t)N2 * D];
__device__ float g_bias[N2];
__device__ uint8_t g_wimg[393216];

// Q0/Q1: fp16 hi/lo images (64KB each). W0/W1: bf16 hi/lo images (128KB each).
#define IMG_Q0 0
#define IMG_W0 65536
#define IMG_Q1 196608
#define IMG_W1 262144

// ---------------- helpers ----------------
__device__ __forceinline__ uint32_t smem_u32(const void* p) {
    uint32_t a;
    asm("{ .reg .u64 t; cvta.to.shared.u64 t, %1; cvt.u32.u64 %0, t; }" : "=r"(a) : "l"(p));
    return a;
}

__device__ __forceinline__ void ldsm4(uint32_t* r, uint32_t addr) {
    asm volatile("ldmatrix.sync.aligned.m8n8.x4.shared.b16 {%0,%1,%2,%3}, [%4];"
                 : "=r"(r[0]), "=r"(r[1]), "=r"(r[2]), "=r"(r[3]) : "r"(addr));
}

__device__ __forceinline__ void mma_bf16(float* c, const uint32_t* a, const uint32_t* b) {
    asm volatile("mma.sync.aligned.m16n8k16.row.col.f32.bf16.bf16.f32 "
                 "{%0,%1,%2,%3}, {%4,%5,%6,%7}, {%8,%9}, {%0,%1,%2,%3};"
                 : "+f"(c[0]), "+f"(c[1]), "+f"(c[2]), "+f"(c[3])
                 : "r"(a[0]), "r"(a[1]), "r"(a[2]), "r"(a[3]), "r"(b[0]), "r"(b[1]));
}

__device__ __forceinline__ void mma_f16(float* c, const uint32_t* a, const uint32_t* b) {
    asm volatile("mma.sync.aligned.m16n8k16.row.col.f32.f16.f16.f32 "
                 "{%0,%1,%2,%3}, {%4,%5,%6,%7}, {%8,%9}, {%0,%1,%2,%3};"
                 : "+f"(c[0]), "+f"(c[1]), "+f"(c[2]), "+f"(c[3])
                 : "r"(a[0]), "r"(a[1]), "r"(a[2]), "r"(a[3]), "r"(b[0]), "r"(b[1]));
}

__device__ __forceinline__ void split2_bf(float a, float b, uint32_t& hi, uint32_t& lo) {
    __nv_bfloat16 ha = __float2bfloat16(a), hb = __float2bfloat16(b);
    float ra = a - __bfloat162float(ha), rb = b - __bfloat162float(hb);
    __nv_bfloat16 la = __float2bfloat16(ra), lb = __float2bfloat16(rb);
    hi = (uint32_t)__bfloat16_as_ushort(ha) | ((uint32_t)__bfloat16_as_ushort(hb) << 16);
    lo = (uint32_t)__bfloat16_as_ushort(la) | ((uint32_t)__bfloat16_as_ushort(lb) << 16);
}

// swizzled byte offset within a (rows x 128)-element 16-bit tile (pitch 256B):
__device__ __forceinline__ uint32_t tswz(int r, int cbyte) {
    return (uint32_t)r * 256u + ((uint32_t)cbyte ^ (((uint32_t)r & 7u) << 4));
}

// ---------------- weight image prep (all 4 weights in one launch) ----------
// fp16 hi/lo (for gemm_scatter's Q weights)
__device__ __forceinline__ void prep_one_f16(const float* __restrict__ W, int Kw,
                                             uint8_t* __restrict__ img, int gid, int gsz) {
    int total = Kw * 128;
    for (int f = gid; f < total; f += gsz) {
        int k = f >> 7, n = f & 127;
        float x = W[f];
        __half h = __float2half_rn(x);
        float r = x - __half2float(h);
        __half l = __float2half_rn(r);
        uint32_t base = tswz(n, k * 2);
        *(__half*)(img + base) = h;
        *(__half*)(img + base + 32768) = l;
    }
}

// bf16 hi/lo (for zconv's W weights, K up to 256 -> 2 chunks)
__device__ __forceinline__ void prep_one_bf16(const float* __restrict__ W, int Kw,
                                              uint8_t* __restrict__ img, int gid, int gsz) {
    int total = Kw * 128;
    for (int f = gid; f < total; f += gsz) {
        int k = f >> 7, n = f & 127;
        int c = k >> 7, kk = k & 127;
        float x = W[f];
        __nv_bfloat16 h = __float2bfloat16(x);
        float r = x - __bfloat162float(h);
        __nv_bfloat16 l = __float2bfloat16(r);
        size_t base = (size_t)c * 65536 + tswz(n, kk * 2);
        *(__nv_bfloat16*)(img + base) = h;
        *(__nv_bfloat16*)(img + base + 32768) = l;
    }
}

__global__ void prep_weight_all(const float* __restrict__ Q0, const float* __restrict__ W0,
                                const float* __restrict__ Q1, const float* __restrict__ W1,
                                uint8_t* __restrict__ img) {
    int gid = blockIdx.x * blockDim.x + threadIdx.x;
    int gsz = gridDim.x * blockDim.x;
    prep_one_f16(Q0, 128, img + IMG_Q0, gid, gsz);
    prep_one_bf16(W0, 256, img + IMG_W0, gid, gsz);
    prep_one_f16(Q1, 128, img + IMG_Q1, gid, gsz);
    prep_one_bf16(W1, 256, img + IMG_W1, gid, gsz);
}

// ---------------- zero ----------------
__global__ void zero_kernel(float4* __restrict__ p, int n4) {
    int i = blockIdx.x * blockDim.x + threadIdx.x;
    if (i < n4) p[i] = make_float4(0.f, 0.f, 0.f, 0.f);
}

// ------- fp16 2-product MMA over one 128-K chunk (MT=2, NP=2) -------
// C += A_f16 x (B_hi + B_lo). acc = float[8][4].
__device__ __forceinline__ void mma_K128_f16(float* acc, uint32_t A,
                                             uint32_t Bh, uint32_t Bl, int lane,
                                             int mb, int nb)
{
    const uint32_t sw = (uint32_t)(lane & 7) << 4;
    const uint32_t arow = (uint32_t)(((lane >> 3) & 1) * 8 + (lane & 7));
    const uint32_t akh = (uint32_t)((lane >> 4) * 16);
    const uint32_t brow = (uint32_t)(((lane >> 4) & 1) * 8 + (lane & 7));
    const uint32_t bkh = (uint32_t)(((lane >> 3) & 1) * 16);

#pragma unroll
    for (int ks = 0; ks < 8; ks++) {
        uint32_t ako = ((uint32_t)(32 * ks) + akh) ^ sw;
        uint32_t bko = ((uint32_t)(32 * ks) + bkh) ^ sw;
        uint32_t a[2][4];
#pragma unroll
        for (int mt = 0; mt < 2; mt++) {
            uint32_t ro = (uint32_t)(mb + mt * 16) * 256u + arow * 256u;
            ldsm4(a[mt], A + ro + ako);
        }
#pragma unroll
        for (int np = 0; np < 2; np++) {
            uint32_t no = (uint32_t)(nb + np * 16) * 256u + brow * 256u;
            uint32_t bh[4], bl[4];
            ldsm4(bh, Bh + no + bko);
            ldsm4(bl, Bl + no + bko);
#pragma unroll
            for (int mt = 0; mt < 2; mt++)
#pragma unroll
                for (int nt = 0; nt < 2; nt++) {
                    float* c = acc + (mt * 4 + np * 2 + nt) * 4;
                    mma_f16(c, a[mt], bh + nt * 2);
                    mma_f16(c, a[mt], bl + nt * 2);
                }
        }
    }
}

// ------- bf16 3-product MMA over one 128-K chunk (MT=2, NP=2) -------
__device__ __forceinline__ void mma_K128_bf(float* acc, uint32_t Ah, uint32_t Al,
                                            uint32_t Bh, uint32_t Bl, int lane,
                                            int mb, int nb)
{
    const uint32_t sw = (uint32_t)(lane & 7) << 4;
    const uint32_t arow = (uint32_t)(((lane >> 3) & 1) * 8 + (lane & 7));
    const uint32_t akh = (uint32_t)((lane >> 4) * 16);
    const uint32_t brow = (uint32_t)(((lane >> 4) & 1) * 8 + (lane & 7));
    const uint32_t bkh = (uint32_t)(((lane >> 3) & 1) * 16);

#pragma unroll
    for (int ks = 0; ks < 8; ks++) {
        uint32_t ako = ((uint32_t)(32 * ks) + akh) ^ sw;
        uint32_t bko = ((uint32_t)(32 * ks) + bkh) ^ sw;
        uint32_t ah[2][4], al[2][4];
#pragma unroll
        for (int mt = 0; mt < 2; mt++) {
            uint32_t ro = (uint32_t)(mb + mt * 16) * 256u + arow * 256u;
            ldsm4(ah[mt], Ah + ro + ako);
            ldsm4(al[mt], Al + ro + ako);
        }
#pragma unroll
        for (int np = 0; np < 2; np++) {
            uint32_t no = (uint32_t)(nb + np * 16) * 256u + brow * 256u;
            uint32_t bh[4], bl[4];
            ldsm4(bh, Bh + no + bko);
            ldsm4(bl, Bl + no + bko);
#pragma unroll
            for (int mt = 0; mt < 2; mt++)
#pragma unroll
                for (int nt = 0; nt < 2; nt++) {
                    float* c = acc + (mt * 4 + np * 2 + nt) * 4;
                    mma_bf16(c, ah[mt], bh + nt * 2);
                    mma_bf16(c, ah[mt], bl + nt * 2);
                    mma_bf16(c, al[mt], bh + nt * 2);
                }
        }
    }
}

// ====== PERSISTENT fused gemm+scatter (M-tile 64, 256 thr / 8 warps,
//        2 CTAs/SM), fp16 2-product, warp tile 32x32, index prefetch =====
// smem: bias 512 @0, wbuf 256 @512, dbuf 256 @768, A @1024 (16K f16),
//       B @17408 (64K: hi 32K, lo 32K) -> total 82944
__global__ __launch_bounds__(256, 2) void gemm_scatter(
    const float* __restrict__ X, const int* __restrict__ nids,
    const int* __restrict__ srcE, const int* __restrict__ dstE,
    const float* __restrict__ wE,
    const uint8_t* __restrict__ bimg, const float* __restrict__ b,
    float* __restrict__ m, float* __restrict__ ws, int numTiles)
{
    extern __shared__ uint8_t sm[];
    const uint32_t sb = smem_u32(sm);
    const int tid = threadIdx.x, wid = tid >> 5, lane = tid & 31;
    const uint32_t A1 = 1024, B1 = 17408;
    float* bsp  = (float*)sm;
    float* wbuf = (float*)(sm + 512);
    int*   dbuf = (int*)(sm + 768);
    const int G = gridDim.x;

    if (tid < 32) ((float4*)bsp)[tid] = ((const float4*)b)[tid];
    for (int i = tid; i < 4096; i += 256)
        ((float4*)(sm + B1))[i] = ((const float4*)bimg)[i];

    const int mb = (wid >> 2) * 32, nb = (wid & 3) * 32;

    // prefetch resolved row indices for first tile
    int srN[8];
    if (blockIdx.x < numTiles) {
        const int row0 = blockIdx.x * 64;
#pragma unroll
        for (int i = 0; i < 8; i++) {
            int e = srcE[row0 + wid + 8 * i];
            srN[i] = nids ? nids[e] : e;
        }
    }

    for (int t = blockIdx.x; t < numTiles; t += G) {
        const int row0 = t * 64;
        if (tid < 64) {
            wbuf[tid] = wE[row0 + tid];
            dbuf[tid] = dstE[row0 + tid];
        }
        // gather + fp16 convert: rows wid+8i, col lane (4 floats -> 2 half2)
#pragma unroll
        for (int i = 0; i < 8; i++) {
            int r = wid + 8 * i;
            float4 v = ((const float4*)(X + (size_t)srN[i] * 128))[lane];
            uint32_t off = tswz(r, lane * 8);
            uint2 hv;
            __half2 h01 = __floats2half2_rn(v.x, v.y);
            __half2 h23 = __floats2half2_rn(v.z, v.w);
            hv.x = *(uint32_t*)&h01;
            hv.y = *(uint32_t*)&h23;
            *(uint2*)(sm + A1 + off) = hv;
        }
        __syncthreads();

        // prefetch indices for next tile (covered by MMA below)
        const int tn = t + G;
        if (tn < numTiles) {
            const int rown = tn * 64;
#pragma unroll
            for (int i = 0; i < 8; i++) {
                int e = srcE[rown + wid + 8 * i];
                srN[i] = nids ? nids[e] : e;
            }
        }

        float acc[32];
#pragma unroll
        for (int i = 0; i < 32; i++) acc[i] = 0.f;
        mma_K128_f16(acc, sb + A1, sb + B1, sb + B1 + 32768, lane, mb, nb);

        // scatter directly from accumulator fragments (warp: 32 rows x 32 cols)
#pragma unroll
        for (int mt = 0; mt < 2; mt++)
#pragma unroll
            for (int h = 0; h < 2; h++) {
                int el = mb + mt * 16 + (lane >> 2) + h * 8;
                int d  = dbuf[el];
                float wt = wbuf[el];
                float* rowp = m + (size_t)d * 128;
#pragma unroll
                for (int g = 0; g < 4; g++) {
                    int c0 = nb + g * 8 + 2 * (lane & 3);
                    float* a4 = acc + (mt * 4 + g) * 4 + h * 2;
                    float v0 = fmaxf(a4[0] + bsp[c0], 0.f) * wt;
                    float v1 = fmaxf(a4[1] + bsp[c0 + 1], 0.f) * wt;
                    asm volatile("red.global.add.v2.f32 [%0], {%1, %2};"
                                 :: "l"(rowp + c0), "f"(v0), "f"(v1) : "memory");
                }
            }
        if (tid < 64) atomicAdd(ws + dbuf[tid], wbuf[tid]);
        __syncthreads();
    }
}

// ======== PERSISTENT zconv (M-tile 128, 512 thr / 16 warps, 1 CTA/SM) ===
//   bf16 3-product. warp tile 32x32 (mg4 x ng4). B fully resident (128K).
// smem: bias 512 @0, ssb 2K @512, A_hi @2560 (32K), A_lo @35328 (32K),
//       B @68096 (128K) -> total 199168
__global__ __launch_bounds__(512, 1) void zconv_mma(
    const float* __restrict__ gm, const float* __restrict__ gws,
    const float* __restrict__ Xd, const int* __restrict__ idxd,
    const uint8_t* __restrict__ bimg, const float* __restrict__ b,
    const float* __restrict__ addX, const int* __restrict__ addIdx,
    const float* __restrict__ biasv, float* __restrict__ bias_out,
    float* __restrict__ out, int numTiles)
{
    extern __shared__ uint8_t sm[];
    const uint32_t sb = smem_u32(sm);
    const int tid = threadIdx.x, wid = tid >> 5, lane = tid & 31;
    const uint32_t A1 = 2560, A2 = 35328, B1 = 68096;
    float* bsp = (float*)sm;
    float* ssb = (float*)(sm + 512);

    if (tid < 32) ((float4*)bsp)[tid] = ((const float4*)b)[tid];
    for (int i = tid; i < 8192; i += 512)
        ((float4*)(sm + B1))[i] = ((const float4*)bimg)[i];

    const int mb = (wid >> 2) * 32, nb = (wid & 3) * 32;
    const int wn = wid & 3;

    for (int t = blockIdx.x; t < numTiles; t += gridDim.x) {
        const int row0 = t * 128;
        float acc[32];
#pragma unroll
        for (int i = 0; i < 32; i++) acc[i] = 0.f;

#pragma unroll
        for (int c = 0; c < 2; c++) {
#pragma unroll
            for (int i = 0; i < 8; i++) {
                int f = tid + 512 * i;
                int r = f >> 5, q = f & 31;
                int row = row0 + r;
                float4 v;
                if (c == 0) {
                    float inv = 1.f / fmaxf(gws[row], 1.f);
                    v = ((const float4*)(gm + (size_t)row * 128))[q];
                    v.x *= inv; v.y *= inv; v.z *= inv; v.w *= inv;
                } else {
                    size_t sr = idxd ? (size_t)idxd[row] : (size_t)row;
                    v = ((const float4*)(Xd + sr * 128))[q];
                }
                uint32_t off = tswz(r, q * 8);
                uint2 hi, lo;
                split2_bf(v.x, v.y, hi.x, lo.x);
                split2_bf(v.z, v.w, hi.y, lo.y);
                *(uint2*)(sm + A1 + off) = hi;
                *(uint2*)(sm + A2 + off) = lo;
            }
            __syncthreads();
            uint32_t Bc = sb + B1 + (uint32_t)c * 65536;
            mma_K128_bf(acc, sb + A1, sb + A2, Bc, Bc + 32768, lane, mb, nb);
            __syncthreads();
        }

        float ss[2][2] = {{0.f, 0.f}, {0.f, 0.f}};
#pragma unroll
        for (int mt = 0; mt < 2; mt++)
#pragma unroll
            for (int g = 0; g < 4; g++) {
                int c0 = nb + g * 8 + 2 * (lane & 3);
                float* a4 = acc + (mt * 4 + g) * 4;
                a4[0] = fmaxf(a4[0] + bsp[c0], 0.f);
                a4[1] = fmaxf(a4[1] + bsp[c0 + 1], 0.f);
                a4[2] = fmaxf(a4[2] + bsp[c0], 0.f);
                a4[3] = fmaxf(a4[3] + bsp[c0 + 1], 0.f);
                ss[mt][0] += a4[0] * a4[0] + a4[1] * a4[1];
                ss[mt][1] += a4[2] * a4[2] + a4[3] * a4[3];
            }
#pragma unroll
        for (int mt = 0; mt < 2; mt++)
#pragma unroll
            for (int h = 0; h < 2; h++) {
                float v = ss[mt][h];
                v += __shfl_xor_sync(0xffffffffu, v, 1);
                v += __shfl_xor_sync(0xffffffffu, v, 2);
                ss[mt][h] = v;
            }
        if ((lane & 3) == 0) {
#pragma unroll
            for (int mt = 0; mt < 2; mt++)
#pragma unroll
                for (int h = 0; h < 2; h++) {
                    int rl = mb + mt * 16 + (lane >> 2) + h * 8;
                    ssb[rl * 4 + wn] = ss[mt][h];
                }
        }
        __syncthreads();

#pragma unroll
        for (int mt = 0; mt < 2; mt++)
#pragma unroll
            for (int h = 0; h < 2; h++) {
                int rl = mb + mt * 16 + (lane >> 2) + h * 8;
                int rg = row0 + rl;
                float tsum = ssb[rl * 4] + ssb[rl * 4 + 1] + ssb[rl * 4 + 2] + ssb[rl * 4 + 3];
                float sc = (tsum > 0.f) ? rsqrtf(tsum) : 1.f;
                int ai = 0;
                if (addIdx) {
                    ai = addIdx[rg];
                    if ((lane & 3) == 0 && wn == 0) bias_out[rg] = biasv[ai];
                }
#pragma unroll
                for (int g = 0; g < 4; g++) {
                    int c0 = nb + g * 8 + 2 * (lane & 3);
                    float* a4 = acc + (mt * 4 + g) * 4 + h * 2;
                    float2 o;
                    o.x = a4[0] * sc;
                    o.y = a4[1] * sc;
                    if (addIdx) {
                        float2 av = *(const float2*)(addX + (size_t)ai * 128 + c0);
                        o.x += av.x; o.y += av.y;
                    }
                    *(float2*)(out + (size_t)rg * 128 + c0) = o;
                }
            }
        __syncthreads();
    }
}

// ---------------- pair scores ----------------
__global__ __launch_bounds__(256) void score_kernel(
    const float* __restrict__ h, const float* __restrict__ bn,
    const int* __restrict__ ps, const int* __restrict__ pd,
    const int* __restrict__ ns, const int* __restrict__ nd,
    float* __restrict__ out)
{
    int e = (blockIdx.x * blockDim.x + threadIdx.x) >> 5;
    if (e >= EP) return;
    int lane = threadIdx.x & 31;
    int a = ps[e], b2 = pd[e], c = ns[e], d2 = nd[e];

    float4 u, v;
    u = ((const float4*)(h + (size_t)a * 128))[lane];
    v = ((const float4*)(h + (size_t)b2 * 128))[lane];
    float sp = u.x * v.x + u.y * v.y + u.z * v.z + u.w * v.w;
    u = ((const float4*)(h + (size_t)c * 128))[lane];
    v = ((const float4*)(h + (size_t)d2 * 128))[lane];
    float sn = u.x * v.x + u.y * v.y + u.z * v.z + u.w * v.w;
#pragma unroll
    for (int o = 16; o; o >>= 1) {
        sp += __shfl_xor_sync(0xffffffffu, sp, o);
        sn += __shfl_xor_sync(0xffffffffu, sn, o);
    }
    if (lane == 0) {
        float pos = sp + bn[a] + bn[b2];
        float neg = sn + bn[c] + bn[d2];
        out[e] = fmaxf(neg - pos + 1.0f, 0.f);
    }
}

// ---------------- launch ----------------
extern "C" void kernel_launch(void* const* d_in, const int* in_sizes, int n_in,
                              void* d_out, int out_size)
{
    const float* emb  = (const float*)d_in[0];
    const float* bias = (const float*)d_in[1];
    const int*   nids = (const int*)d_in[2];
    const int*   src0 = (const int*)d_in[3];
    const int*   dst0 = (const int*)d_in[4];
    const float* w0   = (const float*)d_in[5];
    const int*   src1 = (const int*)d_in[6];
    const int*   dst1 = (const int*)d_in[7];
    const float* w1   = (const float*)d_in[8];
    const int*   pos_src = (const int*)d_in[9];
    const int*   pos_dst = (const int*)d_in[10];
    const int*   neg_src = (const int*)d_in[11];
    const int*   neg_dst = (const int*)d_in[12];
    const float* Q0w = (const float*)d_in[13];
    const float* Q0b = (const float*)d_in[14];
    const float* W0w = (const float*)d_in[15];
    const float* W0b = (const float*)d_in[16];
    const float* Q1w = (const float*)d_in[17];
    const float* Q1b = (const float*)d_in[18];
    const float* W1w = (const float*)d_in[19];
    const float* W1b = (const float*)d_in[20];
    float* out = (float*)d_out;

    float *p_m, *p_ws, *p_h1, *p_hi, *p_b;
    uint8_t* p_img;
    cudaGetSymbolAddress((void**)&p_m,  g_m);
    cudaGetSymbolAddress((void**)&p_ws, g_ws);
    cudaGetSymbolAddress((void**)&p_h1, g_h1);
    cudaGetSymbolAddress((void**)&p_hi, g_hitem);
    cudaGetSymbolAddress((void**)&p_b,  g_bias);
    cudaGetSymbolAddress((void**)&p_img, g_wimg);

    const int SMEM_G = 1024 + 16384 + 65536;                // 82944
    const int SMEM_Z = 2560 + 2 * 32768 + 2 * 65536;        // 199168
    cudaFuncSetAttribute(gemm_scatter, cudaFuncAttributeMaxDynamicSharedMemorySize, SMEM_G);
    cudaFuncSetAttribute(zconv_mma,    cudaFuncAttributeMaxDynamicSharedMemorySize, SMEM_Z);

    prep_weight_all<<<128, 256>>>(Q0w, W0w, Q1w, W1w, p_img);

    const int GS_GRID = 296;
    const int ZC_GRID = 148;

    // layer 0: fused n = relu(emb[nids[src0]] @ Q0 + b0); scatter into m, ws
    zero_kernel<<<(N1 * 32 + 255) / 256, 256>>>((float4*)p_m, N1 * 32);
    zero_kernel<<<(N1 / 4 + 255) / 256, 256>>>((float4*)p_ws, N1 / 4);
    gemm_scatter<<<GS_GRID, 256, SMEM_G>>>(emb, nids, src0, dst0, w0,
                                           p_img + IMG_Q0, Q0b, p_m, p_ws, E0 / 64);

    // h1 = normalize(relu(concat(m/ws, emb[nids]) @ W0 + b0))
    zconv_mma<<<ZC_GRID, 512, SMEM_Z>>>(p_m, p_ws, emb, nids, p_img + IMG_W0, W0b,
                                        nullptr, nullptr, nullptr, nullptr, p_h1,
                                        N1 / 128);

    // layer 1: fused n1 = relu(h1[src1] @ Q1 + b1); scatter into m, ws
    zero_kernel<<<(N2 * 32 + 255) / 256, 256>>>((float4*)p_m, N2 * 32);
    zero_kernel<<<(N2 / 4 + 255) / 256, 256>>>((float4*)p_ws, N2 / 4);
    gemm_scatter<<<GS_GRID, 256, SMEM_G>>>(p_h1, nullptr, src1, dst1, w1,
                                           p_img + IMG_Q1, Q1b, p_m, p_ws, E1 / 64);

    // h_item = emb[nids[:N2]] + normalize(relu(concat(m/ws, h1) @ W1 + b1))
    zconv_mma<<<128, 512, SMEM_Z>>>(p_m, p_ws, p_h1, nullptr, p_img + IMG_W1, W1b,
                                    emb, nids, bias, p_b, p_hi, N2 / 128);

    score_kernel<<<(EP * 32) / 256, 256>>>(p_hi, p_b, pos_src, pos_dst,
                                           neg_src, neg_dst, out);
}

// round 15
// speedup vs baseline: 1.3644x; 1.1499x over previous
#include <cuda_runtime.h>
#include <cuda_bf16.h>
#include <cuda_fp16.h>
#include <cstdint>
#include <cstddef>

#define N0 1048576
#define N1 131072
#define N2 16384
#define E0 1048576
#define E1 131072
#define EP 16384
#define D  128

// ---------------- scratch (device globals; no allocation) ----------------
__device__ float g_m[(size_t)N1 * D];
__device__ float g_ws[N1];
__device__ float g_h1[(size_t)N1 * D];
__device__ float g_hitem[(size_t)N2 * D];
__device__ float g_bias[N2];
__device__ uint8_t g_wimg[393216];

// All images fp16 hi/lo, per 128-K chunk: [hi 32KB][lo 32KB].
#define IMG_Q0 0
#define IMG_W0 65536
#define IMG_Q1 196608
#define IMG_W1 262144

// ---------------- helpers ----------------
__device__ __forceinline__ uint32_t smem_u32(const void* p) {
    uint32_t a;
    asm("{ .reg .u64 t; cvta.to.shared.u64 t, %1; cvt.u32.u64 %0, t; }" : "=r"(a) : "l"(p));
    return a;
}

__device__ __forceinline__ void ldsm4(uint32_t* r, uint32_t addr) {
    asm volatile("ldmatrix.sync.aligned.m8n8.x4.shared.b16 {%0,%1,%2,%3}, [%4];"
                 : "=r"(r[0]), "=r"(r[1]), "=r"(r[2]), "=r"(r[3]) : "r"(addr));
}

__device__ __forceinline__ void mma_f16(float* c, const uint32_t* a, const uint32_t* b) {
    asm volatile("mma.sync.aligned.m16n8k16.row.col.f32.f16.f16.f32 "
                 "{%0,%1,%2,%3}, {%4,%5,%6,%7}, {%8,%9}, {%0,%1,%2,%3};"
                 : "+f"(c[0]), "+f"(c[1]), "+f"(c[2]), "+f"(c[3])
                 : "r"(a[0]), "r"(a[1]), "r"(a[2]), "r"(a[3]), "r"(b[0]), "r"(b[1]));
}

// swizzled byte offset within a (rows x 128)-element 16-bit tile (pitch 256B):
__device__ __forceinline__ uint32_t tswz(int r, int cbyte) {
    return (uint32_t)r * 256u + ((uint32_t)cbyte ^ (((uint32_t)r & 7u) << 4));
}

// ---------------- weight image prep: fp16 hi/lo, chunked (Kw in {128,256}) --
__device__ __forceinline__ void prep_one_f16(const float* __restrict__ W, int Kw,
                                             uint8_t* __restrict__ img, int gid, int gsz) {
    int total = Kw * 128;
    for (int f = gid; f < total; f += gsz) {
        int k = f >> 7, n = f & 127;
        int c = k >> 7, kk = k & 127;
        float x = W[f];
        __half h = __float2half_rn(x);
        __half l = __float2half_rn(x - __half2float(h));
        size_t base = (size_t)c * 65536 + tswz(n, kk * 2);
        *(__half*)(img + base) = h;
        *(__half*)(img + base + 32768) = l;
    }
}

__global__ void prep_weight_all(const float* __restrict__ Q0, const float* __restrict__ W0,
                                const float* __restrict__ Q1, const float* __restrict__ W1,
                                uint8_t* __restrict__ img) {
    int gid = blockIdx.x * blockDim.x + threadIdx.x;
    int gsz = gridDim.x * blockDim.x;
    prep_one_f16(Q0, 128, img + IMG_Q0, gid, gsz);
    prep_one_f16(W0, 256, img + IMG_W0, gid, gsz);
    prep_one_f16(Q1, 128, img + IMG_Q1, gid, gsz);
    prep_one_f16(W1, 256, img + IMG_W1, gid, gsz);
}

// ---------------- zero ----------------
__global__ void zero_kernel(float4* __restrict__ p, int n4) {
    int i = blockIdx.x * blockDim.x + threadIdx.x;
    if (i < n4) p[i] = make_float4(0.f, 0.f, 0.f, 0.f);
}

// ------- fp16 SINGLE-product MMA over one 128-K chunk (MT=2, NP=2) -------
__device__ __forceinline__ void mma_K128_1p(float* acc, uint32_t A, uint32_t Bh,
                                            int lane, int mb, int nb)
{
    const uint32_t sw = (uint32_t)(lane & 7) << 4;
    const uint32_t arow = (uint32_t)(((lane >> 3) & 1) * 8 + (lane & 7));
    const uint32_t akh = (uint32_t)((lane >> 4) * 16);
    const uint32_t brow = (uint32_t)(((lane >> 4) & 1) * 8 + (lane & 7));
    const uint32_t bkh = (uint32_t)(((lane >> 3) & 1) * 16);

#pragma unroll
    for (int ks = 0; ks < 8; ks++) {
        uint32_t ako = ((uint32_t)(32 * ks) + akh) ^ sw;
        uint32_t bko = ((uint32_t)(32 * ks) + bkh) ^ sw;
        uint32_t a[2][4];
#pragma unroll
        for (int mt = 0; mt < 2; mt++) {
            uint32_t ro = (uint32_t)(mb + mt * 16) * 256u + arow * 256u;
            ldsm4(a[mt], A + ro + ako);
        }
#pragma unroll
        for (int np = 0; np < 2; np++) {
            uint32_t no = (uint32_t)(nb + np * 16) * 256u + brow * 256u;
            uint32_t bh[4];
            ldsm4(bh, Bh + no + bko);
#pragma unroll
            for (int mt = 0; mt < 2; mt++)
#pragma unroll
                for (int nt = 0; nt < 2; nt++)
                    mma_f16(acc + (mt * 4 + np * 2 + nt) * 4, a[mt], bh + nt * 2);
        }
    }
}

// ------- fp16 2-product MMA over one 128-K chunk (MT=2, NP=2) -------
__device__ __forceinline__ void mma_K128_2p(float* acc, uint32_t A,
                                            uint32_t Bh, uint32_t Bl,
                                            int lane, int mb, int nb)
{
    const uint32_t sw = (uint32_t)(lane & 7) << 4;
    const uint32_t arow = (uint32_t)(((lane >> 3) & 1) * 8 + (lane & 7));
    const uint32_t akh = (uint32_t)((lane >> 4) * 16);
    const uint32_t brow = (uint32_t)(((lane >> 4) & 1) * 8 + (lane & 7));
    const uint32_t bkh = (uint32_t)(((lane >> 3) & 1) * 16);

#pragma unroll
    for (int ks = 0; ks < 8; ks++) {
        uint32_t ako = ((uint32_t)(32 * ks) + akh) ^ sw;
        uint32_t bko = ((uint32_t)(32 * ks) + bkh) ^ sw;
        uint32_t a[2][4];
#pragma unroll
        for (int mt = 0; mt < 2; mt++) {
            uint32_t ro = (uint32_t)(mb + mt * 16) * 256u + arow * 256u;
            ldsm4(a[mt], A + ro + ako);
        }
#pragma unroll
        for (int np = 0; np < 2; np++) {
            uint32_t no = (uint32_t)(nb + np * 16) * 256u + brow * 256u;
            uint32_t bh[4], bl[4];
            ldsm4(bh, Bh + no + bko);
            ldsm4(bl, Bl + no + bko);
#pragma unroll
            for (int mt = 0; mt < 2; mt++)
#pragma unroll
                for (int nt = 0; nt < 2; nt++) {
                    float* c = acc + (mt * 4 + np * 2 + nt) * 4;
                    mma_f16(c, a[mt], bh + nt * 2);
                    mma_f16(c, a[mt], bl + nt * 2);
                }
        }
    }
}

// ====== PERSISTENT fused gemm+scatter (M-tile 64, 256 thr / 8 warps,
//        2 CTAs/SM), fp16 SINGLE product, warp tile 32x32, index prefetch ===
// smem: bias 512 @0, wbuf 256 @512, dbuf 256 @768, A @1024 (16K f16),
//       B_hi @17408 (32K) -> total 50176
__global__ __launch_bounds__(256, 2) void gemm_scatter(
    const float* __restrict__ X, const int* __restrict__ nids,
    const int* __restrict__ srcE, const int* __restrict__ dstE,
    const float* __restrict__ wE,
    const uint8_t* __restrict__ bimg, const float* __restrict__ b,
    float* __restrict__ m, float* __restrict__ ws, int numTiles)
{
    extern __shared__ uint8_t sm[];
    const uint32_t sb = smem_u32(sm);
    const int tid = threadIdx.x, wid = tid >> 5, lane = tid & 31;
    const uint32_t A1 = 1024, B1 = 17408;
    float* bsp  = (float*)sm;
    float* wbuf = (float*)(sm + 512);
    int*   dbuf = (int*)(sm + 768);
    const int G = gridDim.x;

    if (tid < 32) ((float4*)bsp)[tid] = ((const float4*)b)[tid];
    for (int i = tid; i < 2048; i += 256)   // hi half of image only (32K)
        ((float4*)(sm + B1))[i] = ((const float4*)bimg)[i];

    const int mb = (wid >> 2) * 32, nb = (wid & 3) * 32;

    // prefetch resolved row indices for first tile
    int srN[8];
    if (blockIdx.x < numTiles) {
        const int row0 = blockIdx.x * 64;
#pragma unroll
        for (int i = 0; i < 8; i++) {
            int e = srcE[row0 + wid + 8 * i];
            srN[i] = nids ? nids[e] : e;
        }
    }

    for (int t = blockIdx.x; t < numTiles; t += G) {
        const int row0 = t * 64;
        if (tid < 64) {
            wbuf[tid] = wE[row0 + tid];
            dbuf[tid] = dstE[row0 + tid];
        }
        // gather + fp16 convert: rows wid+8i, col lane
#pragma unroll
        for (int i = 0; i < 8; i++) {
            int r = wid + 8 * i;
            float4 v = ((const float4*)(X + (size_t)srN[i] * 128))[lane];
            uint32_t off = tswz(r, lane * 8);
            uint2 hv;
            __half2 h01 = __floats2half2_rn(v.x, v.y);
            __half2 h23 = __floats2half2_rn(v.z, v.w);
            hv.x = *(uint32_t*)&h01;
            hv.y = *(uint32_t*)&h23;
            *(uint2*)(sm + A1 + off) = hv;
        }
        __syncthreads();

        // prefetch indices for next tile (covered by MMA below)
        const int tn = t + G;
        if (tn < numTiles) {
            const int rown = tn * 64;
#pragma unroll
            for (int i = 0; i < 8; i++) {
                int e = srcE[rown + wid + 8 * i];
                srN[i] = nids ? nids[e] : e;
            }
        }

        float acc[32];
#pragma unroll
        for (int i = 0; i < 32; i++) acc[i] = 0.f;
        mma_K128_1p(acc, sb + A1, sb + B1, lane, mb, nb);

        // scatter directly from accumulator fragments (warp: 32 rows x 32 cols)
#pragma unroll
        for (int mt = 0; mt < 2; mt++)
#pragma unroll
            for (int h = 0; h < 2; h++) {
                int el = mb + mt * 16 + (lane >> 2) + h * 8;
                int d  = dbuf[el];
                float wt = wbuf[el];
                float* rowp = m + (size_t)d * 128;
#pragma unroll
                for (int g = 0; g < 4; g++) {
                    int c0 = nb + g * 8 + 2 * (lane & 3);
                    float* a4 = acc + (mt * 4 + g) * 4 + h * 2;
                    float v0 = fmaxf(a4[0] + bsp[c0], 0.f) * wt;
                    float v1 = fmaxf(a4[1] + bsp[c0 + 1], 0.f) * wt;
                    asm volatile("red.global.add.v2.f32 [%0], {%1, %2};"
                                 :: "l"(rowp + c0), "f"(v0), "f"(v1) : "memory");
                }
            }
        if (tid < 64) atomicAdd(ws + dbuf[tid], wbuf[tid]);
        __syncthreads();
    }
}

// ======== PERSISTENT zconv (M-tile 128, 512 thr / 16 warps, 1 CTA/SM) ===
//   fp16 2-product (A single f16, B hi/lo). warp tile 32x32 (mg4 x ng4).
// smem: bias 512 @0, ssb 2K @512, A @2560 (32K),
//       B @35328 (128K: chunk0 hi/lo, chunk1 hi/lo) -> total 166400
__global__ __launch_bounds__(512, 1) void zconv_mma(
    const float* __restrict__ gm, const float* __restrict__ gws,
    const float* __restrict__ Xd, const int* __restrict__ idxd,
    const uint8_t* __restrict__ bimg, const float* __restrict__ b,
    const float* __restrict__ addX, const int* __restrict__ addIdx,
    const float* __restrict__ biasv, float* __restrict__ bias_out,
    float* __restrict__ out, int numTiles)
{
    extern __shared__ uint8_t sm[];
    const uint32_t sb = smem_u32(sm);
    const int tid = threadIdx.x, wid = tid >> 5, lane = tid & 31;
    const uint32_t A1 = 2560, B1 = 35328;
    float* bsp = (float*)sm;
    float* ssb = (float*)(sm + 512);

    if (tid < 32) ((float4*)bsp)[tid] = ((const float4*)b)[tid];
    for (int i = tid; i < 8192; i += 512)
        ((float4*)(sm + B1))[i] = ((const float4*)bimg)[i];

    const int mb = (wid >> 2) * 32, nb = (wid & 3) * 32;
    const int wn = wid & 3;

    for (int t = blockIdx.x; t < numTiles; t += gridDim.x) {
        const int row0 = t * 128;
        float acc[32];
#pragma unroll
        for (int i = 0; i < 32; i++) acc[i] = 0.f;

#pragma unroll
        for (int c = 0; c < 2; c++) {
#pragma unroll
            for (int i = 0; i < 8; i++) {
                int f = tid + 512 * i;
                int r = f >> 5, q = f & 31;
                int row = row0 + r;
                float4 v;
                if (c == 0) {
                    float inv = 1.f / fmaxf(gws[row], 1.f);
                    v = ((const float4*)(gm + (size_t)row * 128))[q];
                    v.x *= inv; v.y *= inv; v.z *= inv; v.w *= inv;
                } else {
                    size_t sr = idxd ? (size_t)idxd[row] : (size_t)row;
                    v = ((const float4*)(Xd + sr * 128))[q];
                }
                uint32_t off = tswz(r, q * 8);
                uint2 hv;
                __half2 h01 = __floats2half2_rn(v.x, v.y);
                __half2 h23 = __floats2half2_rn(v.z, v.w);
                hv.x = *(uint32_t*)&h01;
                hv.y = *(uint32_t*)&h23;
                *(uint2*)(sm + A1 + off) = hv;
            }
            __syncthreads();
            uint32_t Bc = sb + B1 + (uint32_t)c * 65536;
            mma_K128_2p(acc, sb + A1, Bc, Bc + 32768, lane, mb, nb);
            __syncthreads();
        }

        float ss[2][2] = {{0.f, 0.f}, {0.f, 0.f}};
#pragma unroll
        for (int mt = 0; mt < 2; mt++)
#pragma unroll
            for (int g = 0; g < 4; g++) {
                int c0 = nb + g * 8 + 2 * (lane & 3);
                float* a4 = acc + (mt * 4 + g) * 4;
                a4[0] = fmaxf(a4[0] + bsp[c0], 0.f);
                a4[1] = fmaxf(a4[1] + bsp[c0 + 1], 0.f);
                a4[2] = fmaxf(a4[2] + bsp[c0], 0.f);
                a4[3] = fmaxf(a4[3] + bsp[c0 + 1], 0.f);
                ss[mt][0] += a4[0] * a4[0] + a4[1] * a4[1];
                ss[mt][1] += a4[2] * a4[2] + a4[3] * a4[3];
            }
#pragma unroll
        for (int mt = 0; mt < 2; mt++)
#pragma unroll
            for (int h = 0; h < 2; h++) {
                float v = ss[mt][h];
                v += __shfl_xor_sync(0xffffffffu, v, 1);
                v += __shfl_xor_sync(0xffffffffu, v, 2);
                ss[mt][h] = v;
            }
        if ((lane & 3) == 0) {
#pragma unroll
            for (int mt = 0; mt < 2; mt++)
#pragma unroll
                for (int h = 0; h < 2; h++) {
                    int rl = mb + mt * 16 + (lane >> 2) + h * 8;
                    ssb[rl * 4 + wn] = ss[mt][h];
                }
        }
        __syncthreads();

#pragma unroll
        for (int mt = 0; mt < 2; mt++)
#pragma unroll
            for (int h = 0; h < 2; h++) {
                int rl = mb + mt * 16 + (lane >> 2) + h * 8;
                int rg = row0 + rl;
                float tsum = ssb[rl * 4] + ssb[rl * 4 + 1] + ssb[rl * 4 + 2] + ssb[rl * 4 + 3];
                float sc = (tsum > 0.f) ? rsqrtf(tsum) : 1.f;
                int ai = 0;
                if (addIdx) {
                    ai = addIdx[rg];
                    if ((lane & 3) == 0 && wn == 0) bias_out[rg] = biasv[ai];
                }
#pragma unroll
                for (int g = 0; g < 4; g++) {
                    int c0 = nb + g * 8 + 2 * (lane & 3);
                    float* a4 = acc + (mt * 4 + g) * 4 + h * 2;
                    float2 o;
                    o.x = a4[0] * sc;
                    o.y = a4[1] * sc;
                    if (addIdx) {
                        float2 av = *(const float2*)(addX + (size_t)ai * 128 + c0);
                        o.x += av.x; o.y += av.y;
                    }
                    *(float2*)(out + (size_t)rg * 128 + c0) = o;
                }
            }
        __syncthreads();
    }
}

// ---------------- pair scores ----------------
__global__ __launch_bounds__(256) void score_kernel(
    const float* __restrict__ h, const float* __restrict__ bn,
    const int* __restrict__ ps, const int* __restrict__ pd,
    const int* __restrict__ ns, const int* __restrict__ nd,
    float* __restrict__ out)
{
    int e = (blockIdx.x * blockDim.x + threadIdx.x) >> 5;
    if (e >= EP) return;
    int lane = threadIdx.x & 31;
    int a = ps[e], b2 = pd[e], c = ns[e], d2 = nd[e];

    float4 u, v;
    u = ((const float4*)(h + (size_t)a * 128))[lane];
    v = ((const float4*)(h + (size_t)b2 * 128))[lane];
    float sp = u.x * v.x + u.y * v.y + u.z * v.z + u.w * v.w;
    u = ((const float4*)(h + (size_t)c * 128))[lane];
    v = ((const float4*)(h + (size_t)d2 * 128))[lane];
    float sn = u.x * v.x + u.y * v.y + u.z * v.z + u.w * v.w;
#pragma unroll
    for (int o = 16; o; o >>= 1) {
        sp += __shfl_xor_sync(0xffffffffu, sp, o);
        sn += __shfl_xor_sync(0xffffffffu, sn, o);
    }
    if (lane == 0) {
        float pos = sp + bn[a] + bn[b2];
        float neg = sn + bn[c] + bn[d2];
        out[e] = fmaxf(neg - pos + 1.0f, 0.f);
    }
}

// ---------------- launch ----------------
extern "C" void kernel_launch(void* const* d_in, const int* in_sizes, int n_in,
                              void* d_out, int out_size)
{
    const float* emb  = (const float*)d_in[0];
    const float* bias = (const float*)d_in[1];
    const int*   nids = (const int*)d_in[2];
    const int*   src0 = (const int*)d_in[3];
    const int*   dst0 = (const int*)d_in[4];
    const float* w0   = (const float*)d_in[5];
    const int*   src1 = (const int*)d_in[6];
    const int*   dst1 = (const int*)d_in[7];
    const float* w1   = (const float*)d_in[8];
    const int*   pos_src = (const int*)d_in[9];
    const int*   pos_dst = (const int*)d_in[10];
    const int*   neg_src = (const int*)d_in[11];
    const int*   neg_dst = (const int*)d_in[12];
    const float* Q0w = (const float*)d_in[13];
    const float* Q0b = (const float*)d_in[14];
    const float* W0w = (const float*)d_in[15];
    const float* W0b = (const float*)d_in[16];
    const float* Q1w = (const float*)d_in[17];
    const float* Q1b = (const float*)d_in[18];
    const float* W1w = (const float*)d_in[19];
    const float* W1b = (const float*)d_in[20];
    float* out = (float*)d_out;

    float *p_m, *p_ws, *p_h1, *p_hi, *p_b;
    uint8_t* p_img;
    cudaGetSymbolAddress((void**)&p_m,  g_m);
    cudaGetSymbolAddress((void**)&p_ws, g_ws);
    cudaGetSymbolAddress((void**)&p_h1, g_h1);
    cudaGetSymbolAddress((void**)&p_hi, g_hitem);
    cudaGetSymbolAddress((void**)&p_b,  g_bias);
    cudaGetSymbolAddress((void**)&p_img, g_wimg);

    const int SMEM_G = 1024 + 16384 + 32768;                // 50176
    const int SMEM_Z = 2560 + 32768 + 2 * 65536;            // 166400
    cudaFuncSetAttribute(gemm_scatter, cudaFuncAttributeMaxDynamicSharedMemorySize, SMEM_G);
    cudaFuncSetAttribute(zconv_mma,    cudaFuncAttributeMaxDynamicSharedMemorySize, SMEM_Z);

    prep_weight_all<<<128, 256>>>(Q0w, W0w, Q1w, W1w, p_img);

    const int GS_GRID = 296;
    const int ZC_GRID = 148;

    // layer 0: fused n = relu(emb[nids[src0]] @ Q0 + b0); scatter into m, ws
    zero_kernel<<<(N1 * 32 + 255) / 256, 256>>>((float4*)p_m, N1 * 32);
    zero_kernel<<<(N1 / 4 + 255) / 256, 256>>>((float4*)p_ws, N1 / 4);
    gemm_scatter<<<GS_GRID, 256, SMEM_G>>>(emb, nids, src0, dst0, w0,
                                           p_img + IMG_Q0, Q0b, p_m, p_ws, E0 / 64);

    // h1 = normalize(relu(concat(m/ws, emb[nids]) @ W0 + b0))
    zconv_mma<<<ZC_GRID, 512, SMEM_Z>>>(p_m, p_ws, emb, nids, p_img + IMG_W0, W0b,
                                        nullptr, nullptr, nullptr, nullptr, p_h1,
                                        N1 / 128);

    // layer 1: fused n1 = relu(h1[src1] @ Q1 + b1); scatter into m, ws
    zero_kernel<<<(N2 * 32 + 255) / 256, 256>>>((float4*)p_m, N2 * 32);
    zero_kernel<<<(N2 / 4 + 255) / 256, 256>>>((float4*)p_ws, N2 / 4);
    gemm_scatter<<<GS_GRID, 256, SMEM_G>>>(p_h1, nullptr, src1, dst1, w1,
                                           p_img + IMG_Q1, Q1b, p_m, p_ws, E1 / 64);

    // h_item = emb[nids[:N2]] + normalize(relu(concat(m/ws, h1) @ W1 + b1))
    zconv_mma<<<128, 512, SMEM_Z>>>(p_m, p_ws, p_h1, nullptr, p_img + IMG_W1, W1b,
                                    emb, nids, bias, p_b, p_hi, N2 / 128);

    score_kernel<<<(EP * 32) / 256, 256>>>(p_hi, p_b, pos_src, pos_dst,
                                           neg_src, neg_dst, out);
}

// round 16
// speedup vs baseline: 1.4646x; 1.0734x over previous
#include <cuda_runtime.h>
#include <cuda_bf16.h>
#include <cuda_fp16.h>
#include <cstdint>
#include <cstddef>

#define N0 1048576
#define N1 131072
#define N2 16384
#define E0 1048576
#define E1 131072
#define EP 16384
#define D  128

// ---------------- scratch (device globals; no allocation) ----------------
__device__ float g_m[(size_t)N1 * D];
__device__ float g_ws[N1];
__device__ float g_h1[(size_t)N1 * D];
__device__ float g_hitem[(size_t)N2 * D];
__device__ float g_bias[N2];
__device__ uint8_t g_wimg[393216];

// All images fp16 hi/lo, per 128-K chunk: [hi 32KB][lo 32KB].
#define IMG_Q0 0
#define IMG_W0 65536
#define IMG_Q1 196608
#define IMG_W1 262144

// ---------------- helpers ----------------
__device__ __forceinline__ uint32_t smem_u32(const void* p) {
    uint32_t a;
    asm("{ .reg .u64 t; cvta.to.shared.u64 t, %1; cvt.u32.u64 %0, t; }" : "=r"(a) : "l"(p));
    return a;
}

__device__ __forceinline__ void ldsm4(uint32_t* r, uint32_t addr) {
    asm volatile("ldmatrix.sync.aligned.m8n8.x4.shared.b16 {%0,%1,%2,%3}, [%4];"
                 : "=r"(r[0]), "=r"(r[1]), "=r"(r[2]), "=r"(r[3]) : "r"(addr));
}

__device__ __forceinline__ void mma_f16(float* c, const uint32_t* a, const uint32_t* b) {
    asm volatile("mma.sync.aligned.m16n8k16.row.col.f32.f16.f16.f32 "
                 "{%0,%1,%2,%3}, {%4,%5,%6,%7}, {%8,%9}, {%0,%1,%2,%3};"
                 : "+f"(c[0]), "+f"(c[1]), "+f"(c[2]), "+f"(c[3])
                 : "r"(a[0]), "r"(a[1]), "r"(a[2]), "r"(a[3]), "r"(b[0]), "r"(b[1]));
}

// swizzled byte offset within a (rows x 128)-element 16-bit tile (pitch 256B):
__device__ __forceinline__ uint32_t tswz(int r, int cbyte) {
    return (uint32_t)r * 256u + ((uint32_t)cbyte ^ (((uint32_t)r & 7u) << 4));
}

// ---------------- weight image prep: fp16 hi/lo, chunked (Kw in {128,256}) --
__device__ __forceinline__ void prep_one_f16(const float* __restrict__ W, int Kw,
                                             uint8_t* __restrict__ img, int gid, int gsz) {
    int total = Kw * 128;
    for (int f = gid; f < total; f += gsz) {
        int k = f >> 7, n = f & 127;
        int c = k >> 7, kk = k & 127;
        float x = W[f];
        __half h = __float2half_rn(x);
        __half l = __float2half_rn(x - __half2float(h));
        size_t base = (size_t)c * 65536 + tswz(n, kk * 2);
        *(__half*)(img + base) = h;
        *(__half*)(img + base + 32768) = l;
    }
}

__global__ void prep_weight_all(const float* __restrict__ Q0, const float* __restrict__ W0,
                                const float* __restrict__ Q1, const float* __restrict__ W1,
                                uint8_t* __restrict__ img) {
    int gid = blockIdx.x * blockDim.x + threadIdx.x;
    int gsz = gridDim.x * blockDim.x;
    prep_one_f16(Q0, 128, img + IMG_Q0, gid, gsz);
    prep_one_f16(W0, 256, img + IMG_W0, gid, gsz);
    prep_one_f16(Q1, 128, img + IMG_Q1, gid, gsz);
    prep_one_f16(W1, 256, img + IMG_W1, gid, gsz);
}

// ---------------- zero ----------------
__global__ void zero_kernel(float4* __restrict__ p, int n4) {
    int i = blockIdx.x * blockDim.x + threadIdx.x;
    if (i < n4) p[i] = make_float4(0.f, 0.f, 0.f, 0.f);
}

// ------- fp16 2-product MMA over one 128-K chunk (MT=2, NP=2) -------
__device__ __forceinline__ void mma_K128_2p(float* acc, uint32_t A,
                                            uint32_t Bh, uint32_t Bl,
                                            int lane, int mb, int nb)
{
    const uint32_t sw = (uint32_t)(lane & 7) << 4;
    const uint32_t arow = (uint32_t)(((lane >> 3) & 1) * 8 + (lane & 7));
    const uint32_t akh = (uint32_t)((lane >> 4) * 16);
    const uint32_t brow = (uint32_t)(((lane >> 4) & 1) * 8 + (lane & 7));
    const uint32_t bkh = (uint32_t)(((lane >> 3) & 1) * 16);

#pragma unroll
    for (int ks = 0; ks < 8; ks++) {
        uint32_t ako = ((uint32_t)(32 * ks) + akh) ^ sw;
        uint32_t bko = ((uint32_t)(32 * ks) + bkh) ^ sw;
        uint32_t a[2][4];
#pragma unroll
        for (int mt = 0; mt < 2; mt++) {
            uint32_t ro = (uint32_t)(mb + mt * 16) * 256u + arow * 256u;
            ldsm4(a[mt], A + ro + ako);
        }
#pragma unroll
        for (int np = 0; np < 2; np++) {
            uint32_t no = (uint32_t)(nb + np * 16) * 256u + brow * 256u;
            uint32_t bh[4], bl[4];
            ldsm4(bh, Bh + no + bko);
            ldsm4(bl, Bl + no + bko);
#pragma unroll
            for (int mt = 0; mt < 2; mt++)
#pragma unroll
                for (int nt = 0; nt < 2; nt++) {
                    float* c = acc + (mt * 4 + np * 2 + nt) * 4;
                    mma_f16(c, a[mt], bh + nt * 2);
                    mma_f16(c, a[mt], bl + nt * 2);
                }
        }
    }
}

// ====== PERSISTENT fused gemm+scatter (M-tile 64, 256 thr / 8 warps,
//        2 CTAs/SM), fp16 single product, B FRAGMENTS HOISTED TO REGISTERS ===
// smem: bias 512 @0, wbuf 256 @512, dbuf 256 @768, A @1024 (16K f16),
//       B_hi @17408 (32K, read once) -> total 50176
__global__ __launch_bounds__(256, 2) void gemm_scatter(
    const float* __restrict__ X, const int* __restrict__ nids,
    const int* __restrict__ srcE, const int* __restrict__ dstE,
    const float* __restrict__ wE,
    const uint8_t* __restrict__ bimg, const float* __restrict__ b,
    float* __restrict__ m, float* __restrict__ ws, int numTiles)
{
    extern __shared__ uint8_t sm[];
    const uint32_t sb = smem_u32(sm);
    const int tid = threadIdx.x, wid = tid >> 5, lane = tid & 31;
    const uint32_t A1 = 1024, B1 = 17408;
    float* bsp  = (float*)sm;
    float* wbuf = (float*)(sm + 512);
    int*   dbuf = (int*)(sm + 768);
    const int G = gridDim.x;

    if (tid < 32) ((float4*)bsp)[tid] = ((const float4*)b)[tid];
    for (int i = tid; i < 2048; i += 256)   // hi half of image only (32K)
        ((float4*)(sm + B1))[i] = ((const float4*)bimg)[i];
    __syncthreads();

    const int mb = (wid >> 2) * 32, nb = (wid & 3) * 32;

    // hoist B fragments into registers (loop-invariant): 8ks x 2np x 4 regs
    uint32_t breg[8][2][4];
    {
        const uint32_t sw = (uint32_t)(lane & 7) << 4;
        const uint32_t brow = (uint32_t)(((lane >> 4) & 1) * 8 + (lane & 7));
        const uint32_t bkh = (uint32_t)(((lane >> 3) & 1) * 16);
#pragma unroll
        for (int ks = 0; ks < 8; ks++) {
            uint32_t bko = ((uint32_t)(32 * ks) + bkh) ^ sw;
#pragma unroll
            for (int np = 0; np < 2; np++) {
                uint32_t no = (uint32_t)(nb + np * 16) * 256u + brow * 256u;
                ldsm4(breg[ks][np], sb + B1 + no + bko);
            }
        }
    }

    // A-side ldsm constants
    const uint32_t sw = (uint32_t)(lane & 7) << 4;
    const uint32_t arow = (uint32_t)(((lane >> 3) & 1) * 8 + (lane & 7));
    const uint32_t akh = (uint32_t)((lane >> 4) * 16);

    // prefetch resolved row indices for first tile
    int srN[8];
    if (blockIdx.x < numTiles) {
        const int row0 = blockIdx.x * 64;
#pragma unroll
        for (int i = 0; i < 8; i++) {
            int e = srcE[row0 + wid + 8 * i];
            srN[i] = nids ? nids[e] : e;
        }
    }

    for (int t = blockIdx.x; t < numTiles; t += G) {
        const int row0 = t * 64;
        if (tid < 64) {
            wbuf[tid] = wE[row0 + tid];
            dbuf[tid] = dstE[row0 + tid];
        }
        // gather + fp16 convert: rows wid+8i, col lane
#pragma unroll
        for (int i = 0; i < 8; i++) {
            int r = wid + 8 * i;
            float4 v = ((const float4*)(X + (size_t)srN[i] * 128))[lane];
            uint32_t off = tswz(r, lane * 8);
            uint2 hv;
            __half2 h01 = __floats2half2_rn(v.x, v.y);
            __half2 h23 = __floats2half2_rn(v.z, v.w);
            hv.x = *(uint32_t*)&h01;
            hv.y = *(uint32_t*)&h23;
            *(uint2*)(sm + A1 + off) = hv;
        }
        __syncthreads();

        // prefetch indices for next tile (covered by MMA below)
        const int tn = t + G;
        if (tn < numTiles) {
            const int rown = tn * 64;
#pragma unroll
            for (int i = 0; i < 8; i++) {
                int e = srcE[rown + wid + 8 * i];
                srN[i] = nids ? nids[e] : e;
            }
        }

        float acc[32];
#pragma unroll
        for (int i = 0; i < 32; i++) acc[i] = 0.f;

        // MMA: A from SMEM (ldsm), B from registers
#pragma unroll
        for (int ks = 0; ks < 8; ks++) {
            uint32_t ako = ((uint32_t)(32 * ks) + akh) ^ sw;
            uint32_t a[2][4];
#pragma unroll
            for (int mt = 0; mt < 2; mt++) {
                uint32_t ro = (uint32_t)(mb + mt * 16) * 256u + arow * 256u;
                ldsm4(a[mt], sb + A1 + ro + ako);
            }
#pragma unroll
            for (int np = 0; np < 2; np++)
#pragma unroll
                for (int mt = 0; mt < 2; mt++)
#pragma unroll
                    for (int nt = 0; nt < 2; nt++)
                        mma_f16(acc + (mt * 4 + np * 2 + nt) * 4,
                                a[mt], breg[ks][np] + nt * 2);
        }

        // scatter directly from accumulator fragments (warp: 32 rows x 32 cols)
#pragma unroll
        for (int mt = 0; mt < 2; mt++)
#pragma unroll
            for (int h = 0; h < 2; h++) {
                int el = mb + mt * 16 + (lane >> 2) + h * 8;
                int d  = dbuf[el];
                float wt = wbuf[el];
                float* rowp = m + (size_t)d * 128;
#pragma unroll
                for (int g = 0; g < 4; g++) {
                    int c0 = nb + g * 8 + 2 * (lane & 3);
                    float* a4 = acc + (mt * 4 + g) * 4 + h * 2;
                    float v0 = fmaxf(a4[0] + bsp[c0], 0.f) * wt;
                    float v1 = fmaxf(a4[1] + bsp[c0 + 1], 0.f) * wt;
                    asm volatile("red.global.add.v2.f32 [%0], {%1, %2};"
                                 :: "l"(rowp + c0), "f"(v0), "f"(v1) : "memory");
                }
            }
        if (tid < 64) atomicAdd(ws + dbuf[tid], wbuf[tid]);
        __syncthreads();
    }
}

// ======== PERSISTENT zconv (M-tile 128, 512 thr / 16 warps, 1 CTA/SM) ===
//   fp16 2-product (A single f16, B hi/lo). warp tile 32x32 (mg4 x ng4).
// smem: bias 512 @0, ssb 2K @512, A @2560 (32K),
//       B @35328 (128K: chunk0 hi/lo, chunk1 hi/lo) -> total 166400
__global__ __launch_bounds__(512, 1) void zconv_mma(
    const float* __restrict__ gm, const float* __restrict__ gws,
    const float* __restrict__ Xd, const int* __restrict__ idxd,
    const uint8_t* __restrict__ bimg, const float* __restrict__ b,
    const float* __restrict__ addX, const int* __restrict__ addIdx,
    const float* __restrict__ biasv, float* __restrict__ bias_out,
    float* __restrict__ out, int numTiles)
{
    extern __shared__ uint8_t sm[];
    const uint32_t sb = smem_u32(sm);
    const int tid = threadIdx.x, wid = tid >> 5, lane = tid & 31;
    const uint32_t A1 = 2560, B1 = 35328;
    float* bsp = (float*)sm;
    float* ssb = (float*)(sm + 512);

    if (tid < 32) ((float4*)bsp)[tid] = ((const float4*)b)[tid];
    for (int i = tid; i < 8192; i += 512)
        ((float4*)(sm + B1))[i] = ((const float4*)bimg)[i];

    const int mb = (wid >> 2) * 32, nb = (wid & 3) * 32;
    const int wn = wid & 3;

    for (int t = blockIdx.x; t < numTiles; t += gridDim.x) {
        const int row0 = t * 128;
        float acc[32];
#pragma unroll
        for (int i = 0; i < 32; i++) acc[i] = 0.f;

#pragma unroll
        for (int c = 0; c < 2; c++) {
#pragma unroll
            for (int i = 0; i < 8; i++) {
                int f = tid + 512 * i;
                int r = f >> 5, q = f & 31;
                int row = row0 + r;
                float4 v;
                if (c == 0) {
                    float inv = 1.f / fmaxf(gws[row], 1.f);
                    v = ((const float4*)(gm + (size_t)row * 128))[q];
                    v.x *= inv; v.y *= inv; v.z *= inv; v.w *= inv;
                } else {
                    size_t sr = idxd ? (size_t)idxd[row] : (size_t)row;
                    v = ((const float4*)(Xd + sr * 128))[q];
                }
                uint32_t off = tswz(r, q * 8);
                uint2 hv;
                __half2 h01 = __floats2half2_rn(v.x, v.y);
                __half2 h23 = __floats2half2_rn(v.z, v.w);
                hv.x = *(uint32_t*)&h01;
                hv.y = *(uint32_t*)&h23;
                *(uint2*)(sm + A1 + off) = hv;
            }
            __syncthreads();
            uint32_t Bc = sb + B1 + (uint32_t)c * 65536;
            mma_K128_2p(acc, sb + A1, Bc, Bc + 32768, lane, mb, nb);
            __syncthreads();
        }

        float ss[2][2] = {{0.f, 0.f}, {0.f, 0.f}};
#pragma unroll
        for (int mt = 0; mt < 2; mt++)
#pragma unroll
            for (int g = 0; g < 4; g++) {
                int c0 = nb + g * 8 + 2 * (lane & 3);
                float* a4 = acc + (mt * 4 + g) * 4;
                a4[0] = fmaxf(a4[0] + bsp[c0], 0.f);
                a4[1] = fmaxf(a4[1] + bsp[c0 + 1], 0.f);
                a4[2] = fmaxf(a4[2] + bsp[c0], 0.f);
                a4[3] = fmaxf(a4[3] + bsp[c0 + 1], 0.f);
                ss[mt][0] += a4[0] * a4[0] + a4[1] * a4[1];
                ss[mt][1] += a4[2] * a4[2] + a4[3] * a4[3];
            }
#pragma unroll
        for (int mt = 0; mt < 2; mt++)
#pragma unroll
            for (int h = 0; h < 2; h++) {
                float v = ss[mt][h];
                v += __shfl_xor_sync(0xffffffffu, v, 1);
                v += __shfl_xor_sync(0xffffffffu, v, 2);
                ss[mt][h] = v;
            }
        if ((lane & 3) == 0) {
#pragma unroll
            for (int mt = 0; mt < 2; mt++)
#pragma unroll
                for (int h = 0; h < 2; h++) {
                    int rl = mb + mt * 16 + (lane >> 2) + h * 8;
                    ssb[rl * 4 + wn] = ss[mt][h];
                }
        }
        __syncthreads();

#pragma unroll
        for (int mt = 0; mt < 2; mt++)
#pragma unroll
            for (int h = 0; h < 2; h++) {
                int rl = mb + mt * 16 + (lane >> 2) + h * 8;
                int rg = row0 + rl;
                float tsum = ssb[rl * 4] + ssb[rl * 4 + 1] + ssb[rl * 4 + 2] + ssb[rl * 4 + 3];
                float sc = (tsum > 0.f) ? rsqrtf(tsum) : 1.f;
                int ai = 0;
                if (addIdx) {
                    ai = addIdx[rg];
                    if ((lane & 3) == 0 && wn == 0) bias_out[rg] = biasv[ai];
                }
#pragma unroll
                for (int g = 0; g < 4; g++) {
                    int c0 = nb + g * 8 + 2 * (lane & 3);
                    float* a4 = acc + (mt * 4 + g) * 4 + h * 2;
                    float2 o;
                    o.x = a4[0] * sc;
                    o.y = a4[1] * sc;
                    if (addIdx) {
                        float2 av = *(const float2*)(addX + (size_t)ai * 128 + c0);
                        o.x += av.x; o.y += av.y;
                    }
                    *(float2*)(out + (size_t)rg * 128 + c0) = o;
                }
            }
        __syncthreads();
    }
}

// ---------------- pair scores ----------------
__global__ __launch_bounds__(256) void score_kernel(
    const float* __restrict__ h, const float* __restrict__ bn,
    const int* __restrict__ ps, const int* __restrict__ pd,
    const int* __restrict__ ns, const int* __restrict__ nd,
    float* __restrict__ out)
{
    int e = (blockIdx.x * blockDim.x + threadIdx.x) >> 5;
    if (e >= EP) return;
    int lane = threadIdx.x & 31;
    int a = ps[e], b2 = pd[e], c = ns[e], d2 = nd[e];

    float4 u, v;
    u = ((const float4*)(h + (size_t)a * 128))[lane];
    v = ((const float4*)(h + (size_t)b2 * 128))[lane];
    float sp = u.x * v.x + u.y * v.y + u.z * v.z + u.w * v.w;
    u = ((const float4*)(h + (size_t)c * 128))[lane];
    v = ((const float4*)(h + (size_t)d2 * 128))[lane];
    float sn = u.x * v.x + u.y * v.y + u.z * v.z + u.w * v.w;
#pragma unroll
    for (int o = 16; o; o >>= 1) {
        sp += __shfl_xor_sync(0xffffffffu, sp, o);
        sn += __shfl_xor_sync(0xffffffffu, sn, o);
    }
    if (lane == 0) {
        float pos = sp + bn[a] + bn[b2];
        float neg = sn + bn[c] + bn[d2];
        out[e] = fmaxf(neg - pos + 1.0f, 0.f);
    }
}

// ---------------- launch ----------------
extern "C" void kernel_launch(void* const* d_in, const int* in_sizes, int n_in,
                              void* d_out, int out_size)
{
    const float* emb  = (const float*)d_in[0];
    const float* bias = (const float*)d_in[1];
    const int*   nids = (const int*)d_in[2];
    const int*   src0 = (const int*)d_in[3];
    const int*   dst0 = (const int*)d_in[4];
    const float* w0   = (const float*)d_in[5];
    const int*   src1 = (const int*)d_in[6];
    const int*   dst1 = (const int*)d_in[7];
    const float* w1   = (const float*)d_in[8];
    const int*   pos_src = (const int*)d_in[9];
    const int*   pos_dst = (const int*)d_in[10];
    const int*   neg_src = (const int*)d_in[11];
    const int*   neg_dst = (const int*)d_in[12];
    const float* Q0w = (const float*)d_in[13];
    const float* Q0b = (const float*)d_in[14];
    const float* W0w = (const float*)d_in[15];
    const float* W0b = (const float*)d_in[16];
    const float* Q1w = (const float*)d_in[17];
    const float* Q1b = (const float*)d_in[18];
    const float* W1w = (const float*)d_in[19];
    const float* W1b = (const float*)d_in[20];
    float* out = (float*)d_out;

    float *p_m, *p_ws, *p_h1, *p_hi, *p_b;
    uint8_t* p_img;
    cudaGetSymbolAddress((void**)&p_m,  g_m);
    cudaGetSymbolAddress((void**)&p_ws, g_ws);
    cudaGetSymbolAddress((void**)&p_h1, g_h1);
    cudaGetSymbolAddress((void**)&p_hi, g_hitem);
    cudaGetSymbolAddress((void**)&p_b,  g_bias);
    cudaGetSymbolAddress((void**)&p_img, g_wimg);

    const int SMEM_G = 1024 + 16384 + 32768;                // 50176
    const int SMEM_Z = 2560 + 32768 + 2 * 65536;            // 166400
    cudaFuncSetAttribute(gemm_scatter, cudaFuncAttributeMaxDynamicSharedMemorySize, SMEM_G);
    cudaFuncSetAttribute(zconv_mma,    cudaFuncAttributeMaxDynamicSharedMemorySize, SMEM_Z);

    prep_weight_all<<<128, 256>>>(Q0w, W0w, Q1w, W1w, p_img);

    const int GS_GRID = 296;
    const int ZC_GRID = 148;

    // layer 0: fused n = relu(emb[nids[src0]] @ Q0 + b0); scatter into m, ws
    zero_kernel<<<(N1 * 32 + 255) / 256, 256>>>((float4*)p_m, N1 * 32);
    zero_kernel<<<(N1 / 4 + 255) / 256, 256>>>((float4*)p_ws, N1 / 4);
    gemm_scatter<<<GS_GRID, 256, SMEM_G>>>(emb, nids, src0, dst0, w0,
                                           p_img + IMG_Q0, Q0b, p_m, p_ws, E0 / 64);

    // h1 = normalize(relu(concat(m/ws, emb[nids]) @ W0 + b0))
    zconv_mma<<<ZC_GRID, 512, SMEM_Z>>>(p_m, p_ws, emb, nids, p_img + IMG_W0, W0b,
                                        nullptr, nullptr, nullptr, nullptr, p_h1,
                                        N1 / 128);

    // layer 1: fused n1 = relu(h1[src1] @ Q1 + b1); scatter into m, ws
    zero_kernel<<<(N2 * 32 + 255) / 256, 256>>>((float4*)p_m, N2 * 32);
    zero_kernel<<<(N2 / 4 + 255) / 256, 256>>>((float4*)p_ws, N2 / 4);
    gemm_scatter<<<GS_GRID, 256, SMEM_G>>>(p_h1, nullptr, src1, dst1, w1,
                                           p_img + IMG_Q1, Q1b, p_m, p_ws, E1 / 64);

    // h_item = emb[nids[:N2]] + normalize(relu(concat(m/ws, h1) @ W1 + b1))
    zconv_mma<<<128, 512, SMEM_Z>>>(p_m, p_ws, p_h1, nullptr, p_img + IMG_W1, W1b,
                                    emb, nids, bias, p_b, p_hi, N2 / 128);

    score_kernel<<<(EP * 32) / 256, 256>>>(p_hi, p_b, pos_src, pos_dst,
                                           neg_src, neg_dst, out);
}

// round 17
// speedup vs baseline: 1.5650x; 1.0685x over previous
#include <cuda_runtime.h>
#include <cuda_bf16.h>
#include <cuda_fp16.h>
#include <cstdint>
#include <cstddef>

#define N0 1048576
#define N1 131072
#define N2 16384
#define E0 1048576
#define E1 131072
#define EP 16384
#define D  128

// ---------------- scratch (device globals; no allocation) ----------------
__device__ float g_m[(size_t)N1 * D];
__device__ float g_ws[N1];
__device__ float g_h1[(size_t)N1 * D];
__device__ float g_hitem[(size_t)N2 * D];
__device__ float g_bias[N2];
__device__ uint8_t g_wimg[393216];

// All images fp16 hi/lo, per 128-K chunk: [hi 32KB][lo 32KB].
#define IMG_Q0 0
#define IMG_W0 65536
#define IMG_Q1 196608
#define IMG_W1 262144

// ---------------- helpers ----------------
__device__ __forceinline__ uint32_t smem_u32(const void* p) {
    uint32_t a;
    asm("{ .reg .u64 t; cvta.to.shared.u64 t, %1; cvt.u32.u64 %0, t; }" : "=r"(a) : "l"(p));
    return a;
}

__device__ __forceinline__ void ldsm4(uint32_t* r, uint32_t addr) {
    asm volatile("ldmatrix.sync.aligned.m8n8.x4.shared.b16 {%0,%1,%2,%3}, [%4];"
                 : "=r"(r[0]), "=r"(r[1]), "=r"(r[2]), "=r"(r[3]) : "r"(addr));
}

__device__ __forceinline__ void mma_f16(float* c, const uint32_t* a, const uint32_t* b) {
    asm volatile("mma.sync.aligned.m16n8k16.row.col.f32.f16.f16.f32 "
                 "{%0,%1,%2,%3}, {%4,%5,%6,%7}, {%8,%9}, {%0,%1,%2,%3};"
                 : "+f"(c[0]), "+f"(c[1]), "+f"(c[2]), "+f"(c[3])
                 : "r"(a[0]), "r"(a[1]), "r"(a[2]), "r"(a[3]), "r"(b[0]), "r"(b[1]));
}

// swizzled byte offset within a (rows x 128)-element 16-bit tile (pitch 256B):
__device__ __forceinline__ uint32_t tswz(int r, int cbyte) {
    return (uint32_t)r * 256u + ((uint32_t)cbyte ^ (((uint32_t)r & 7u) << 4));
}

// ---------------- weight image prep: fp16 hi/lo, chunked (Kw in {128,256}) --
__device__ __forceinline__ void prep_one_f16(const float* __restrict__ W, int Kw,
                                             uint8_t* __restrict__ img, int gid, int gsz) {
    int total = Kw * 128;
    for (int f = gid; f < total; f += gsz) {
        int k = f >> 7, n = f & 127;
        int c = k >> 7, kk = k & 127;
        float x = W[f];
        __half h = __float2half_rn(x);
        __half l = __float2half_rn(x - __half2float(h));
        size_t base = (size_t)c * 65536 + tswz(n, kk * 2);
        *(__half*)(img + base) = h;
        *(__half*)(img + base + 32768) = l;
    }
}

__global__ void prep_weight_all(const float* __restrict__ Q0, const float* __restrict__ W0,
                                const float* __restrict__ Q1, const float* __restrict__ W1,
                                uint8_t* __restrict__ img) {
    int gid = blockIdx.x * blockDim.x + threadIdx.x;
    int gsz = gridDim.x * blockDim.x;
    prep_one_f16(Q0, 128, img + IMG_Q0, gid, gsz);
    prep_one_f16(W0, 256, img + IMG_W0, gid, gsz);
    prep_one_f16(Q1, 128, img + IMG_Q1, gid, gsz);
    prep_one_f16(W1, 256, img + IMG_W1, gid, gsz);
}

// ---------------- zero ----------------
__global__ void zero_kernel(float4* __restrict__ p, int n4) {
    int i = blockIdx.x * blockDim.x + threadIdx.x;
    if (i < n4) p[i] = make_float4(0.f, 0.f, 0.f, 0.f);
}

// ------- fp16 SINGLE-product MMA over one 128-K chunk (MT=2, NP=2) -------
__device__ __forceinline__ void mma_K128_1p(float* acc, uint32_t A, uint32_t Bh,
                                            int lane, int mb, int nb)
{
    const uint32_t sw = (uint32_t)(lane & 7) << 4;
    const uint32_t arow = (uint32_t)(((lane >> 3) & 1) * 8 + (lane & 7));
    const uint32_t akh = (uint32_t)((lane >> 4) * 16);
    const uint32_t brow = (uint32_t)(((lane >> 4) & 1) * 8 + (lane & 7));
    const uint32_t bkh = (uint32_t)(((lane >> 3) & 1) * 16);

#pragma unroll
    for (int ks = 0; ks < 8; ks++) {
        uint32_t ako = ((uint32_t)(32 * ks) + akh) ^ sw;
        uint32_t bko = ((uint32_t)(32 * ks) + bkh) ^ sw;
        uint32_t a[2][4];
#pragma unroll
        for (int mt = 0; mt < 2; mt++) {
            uint32_t ro = (uint32_t)(mb + mt * 16) * 256u + arow * 256u;
            ldsm4(a[mt], A + ro + ako);
        }
#pragma unroll
        for (int np = 0; np < 2; np++) {
            uint32_t no = (uint32_t)(nb + np * 16) * 256u + brow * 256u;
            uint32_t bh[4];
            ldsm4(bh, Bh + no + bko);
#pragma unroll
            for (int mt = 0; mt < 2; mt++)
#pragma unroll
                for (int nt = 0; nt < 2; nt++)
                    mma_f16(acc + (mt * 4 + np * 2 + nt) * 4, a[mt], bh + nt * 2);
        }
    }
}

// ====== PERSISTENT fused gemm+scatter (M-tile 64, 256 thr / 8 warps,
//        2 CTAs/SM), fp16 single product, B FRAGMENTS HOISTED TO REGISTERS ===
// smem: bias 512 @0, wbuf 256 @512, dbuf 256 @768, A @1024 (16K f16),
//       B_hi @17408 (32K, read once) -> total 50176
__global__ __launch_bounds__(256, 2) void gemm_scatter(
    const float* __restrict__ X, const int* __restrict__ nids,
    const int* __restrict__ srcE, const int* __restrict__ dstE,
    const float* __restrict__ wE,
    const uint8_t* __restrict__ bimg, const float* __restrict__ b,
    float* __restrict__ m, float* __restrict__ ws, int numTiles)
{
    extern __shared__ uint8_t sm[];
    const uint32_t sb = smem_u32(sm);
    const int tid = threadIdx.x, wid = tid >> 5, lane = tid & 31;
    const uint32_t A1 = 1024, B1 = 17408;
    float* bsp  = (float*)sm;
    float* wbuf = (float*)(sm + 512);
    int*   dbuf = (int*)(sm + 768);
    const int G = gridDim.x;

    if (tid < 32) ((float4*)bsp)[tid] = ((const float4*)b)[tid];
    for (int i = tid; i < 2048; i += 256)   // hi half of image only (32K)
        ((float4*)(sm + B1))[i] = ((const float4*)bimg)[i];
    __syncthreads();

    const int mb = (wid >> 2) * 32, nb = (wid & 3) * 32;

    // hoist B fragments into registers (loop-invariant): 8ks x 2np x 4 regs
    uint32_t breg[8][2][4];
    {
        const uint32_t sw = (uint32_t)(lane & 7) << 4;
        const uint32_t brow = (uint32_t)(((lane >> 4) & 1) * 8 + (lane & 7));
        const uint32_t bkh = (uint32_t)(((lane >> 3) & 1) * 16);
#pragma unroll
        for (int ks = 0; ks < 8; ks++) {
            uint32_t bko = ((uint32_t)(32 * ks) + bkh) ^ sw;
#pragma unroll
            for (int np = 0; np < 2; np++) {
                uint32_t no = (uint32_t)(nb + np * 16) * 256u + brow * 256u;
                ldsm4(breg[ks][np], sb + B1 + no + bko);
            }
        }
    }

    // A-side ldsm constants
    const uint32_t sw = (uint32_t)(lane & 7) << 4;
    const uint32_t arow = (uint32_t)(((lane >> 3) & 1) * 8 + (lane & 7));
    const uint32_t akh = (uint32_t)((lane >> 4) * 16);

    // prefetch resolved row indices for first tile
    int srN[8];
    if (blockIdx.x < numTiles) {
        const int row0 = blockIdx.x * 64;
#pragma unroll
        for (int i = 0; i < 8; i++) {
            int e = srcE[row0 + wid + 8 * i];
            srN[i] = nids ? nids[e] : e;
        }
    }

    for (int t = blockIdx.x; t < numTiles; t += G) {
        const int row0 = t * 64;
        if (tid < 64) {
            wbuf[tid] = wE[row0 + tid];
            dbuf[tid] = dstE[row0 + tid];
        }
        // gather + fp16 convert: rows wid+8i, col lane
#pragma unroll
        for (int i = 0; i < 8; i++) {
            int r = wid + 8 * i;
            float4 v = ((const float4*)(X + (size_t)srN[i] * 128))[lane];
            uint32_t off = tswz(r, lane * 8);
            uint2 hv;
            __half2 h01 = __floats2half2_rn(v.x, v.y);
            __half2 h23 = __floats2half2_rn(v.z, v.w);
            hv.x = *(uint32_t*)&h01;
            hv.y = *(uint32_t*)&h23;
            *(uint2*)(sm + A1 + off) = hv;
        }
        __syncthreads();

        // prefetch indices for next tile (covered by MMA below)
        const int tn = t + G;
        if (tn < numTiles) {
            const int rown = tn * 64;
#pragma unroll
            for (int i = 0; i < 8; i++) {
                int e = srcE[rown + wid + 8 * i];
                srN[i] = nids ? nids[e] : e;
            }
        }

        float acc[32];
#pragma unroll
        for (int i = 0; i < 32; i++) acc[i] = 0.f;

        // MMA: A from SMEM (ldsm), B from registers
#pragma unroll
        for (int ks = 0; ks < 8; ks++) {
            uint32_t ako = ((uint32_t)(32 * ks) + akh) ^ sw;
            uint32_t a[2][4];
#pragma unroll
            for (int mt = 0; mt < 2; mt++) {
                uint32_t ro = (uint32_t)(mb + mt * 16) * 256u + arow * 256u;
                ldsm4(a[mt], sb + A1 + ro + ako);
            }
#pragma unroll
            for (int np = 0; np < 2; np++)
#pragma unroll
                for (int mt = 0; mt < 2; mt++)
#pragma unroll
                    for (int nt = 0; nt < 2; nt++)
                        mma_f16(acc + (mt * 4 + np * 2 + nt) * 4,
                                a[mt], breg[ks][np] + nt * 2);
        }

        // scatter directly from accumulator fragments (warp: 32 rows x 32 cols)
#pragma unroll
        for (int mt = 0; mt < 2; mt++)
#pragma unroll
            for (int h = 0; h < 2; h++) {
                int el = mb + mt * 16 + (lane >> 2) + h * 8;
                int d  = dbuf[el];
                float wt = wbuf[el];
                float* rowp = m + (size_t)d * 128;
#pragma unroll
                for (int g = 0; g < 4; g++) {
                    int c0 = nb + g * 8 + 2 * (lane & 3);
                    float* a4 = acc + (mt * 4 + g) * 4 + h * 2;
                    float v0 = fmaxf(a4[0] + bsp[c0], 0.f) * wt;
                    float v1 = fmaxf(a4[1] + bsp[c0 + 1], 0.f) * wt;
                    asm volatile("red.global.add.v2.f32 [%0], {%1, %2};"
                                 :: "l"(rowp + c0), "f"(v0), "f"(v1) : "memory");
                }
            }
        if (tid < 64) atomicAdd(ws + dbuf[tid], wbuf[tid]);
        __syncthreads();
    }
}

// ======== PERSISTENT zconv (M-tile 128, 512 thr / 16 warps, 1 CTA/SM) ===
//   fp16 SINGLE product (A f16, B hi only). warp tile 32x32 (mg4 x ng4).
// smem: bias 512 @0, ssb 2K @512, A @2560 (32K),
//       B @35328 (64K: chunk0 hi, chunk1 hi) -> total 100864
__global__ __launch_bounds__(512, 1) void zconv_mma(
    const float* __restrict__ gm, const float* __restrict__ gws,
    const float* __restrict__ Xd, const int* __restrict__ idxd,
    const uint8_t* __restrict__ bimg, const float* __restrict__ b,
    const float* __restrict__ addX, const int* __restrict__ addIdx,
    const float* __restrict__ biasv, float* __restrict__ bias_out,
    float* __restrict__ out, int numTiles)
{
    extern __shared__ uint8_t sm[];
    const uint32_t sb = smem_u32(sm);
    const int tid = threadIdx.x, wid = tid >> 5, lane = tid & 31;
    const uint32_t A1 = 2560, B1 = 35328;
    float* bsp = (float*)sm;
    float* ssb = (float*)(sm + 512);

    if (tid < 32) ((float4*)bsp)[tid] = ((const float4*)b)[tid];
    // load only the hi halves of the two K-chunks (32K each)
    for (int i = tid; i < 2048; i += 512) {
        ((float4*)(sm + B1))[i]        = ((const float4*)bimg)[i];          // chunk0 hi
        ((float4*)(sm + B1))[2048 + i] = ((const float4*)bimg)[4096 + i];   // chunk1 hi
    }

    const int mb = (wid >> 2) * 32, nb = (wid & 3) * 32;
    const int wn = wid & 3;

    for (int t = blockIdx.x; t < numTiles; t += gridDim.x) {
        const int row0 = t * 128;
        float acc[32];
#pragma unroll
        for (int i = 0; i < 32; i++) acc[i] = 0.f;

#pragma unroll
        for (int c = 0; c < 2; c++) {
#pragma unroll
            for (int i = 0; i < 8; i++) {
                int f = tid + 512 * i;
                int r = f >> 5, q = f & 31;
                int row = row0 + r;
                float4 v;
                if (c == 0) {
                    float inv = 1.f / fmaxf(gws[row], 1.f);
                    v = ((const float4*)(gm + (size_t)row * 128))[q];
                    v.x *= inv; v.y *= inv; v.z *= inv; v.w *= inv;
                } else {
                    size_t sr = idxd ? (size_t)idxd[row] : (size_t)row;
                    v = ((const float4*)(Xd + sr * 128))[q];
                }
                uint32_t off = tswz(r, q * 8);
                uint2 hv;
                __half2 h01 = __floats2half2_rn(v.x, v.y);
                __half2 h23 = __floats2half2_rn(v.z, v.w);
                hv.x = *(uint32_t*)&h01;
                hv.y = *(uint32_t*)&h23;
                *(uint2*)(sm + A1 + off) = hv;
            }
            __syncthreads();
            uint32_t Bc = sb + B1 + (uint32_t)c * 32768;
            mma_K128_1p(acc, sb + A1, Bc, lane, mb, nb);
            __syncthreads();
        }

        float ss[2][2] = {{0.f, 0.f}, {0.f, 0.f}};
#pragma unroll
        for (int mt = 0; mt < 2; mt++)
#pragma unroll
            for (int g = 0; g < 4; g++) {
                int c0 = nb + g * 8 + 2 * (lane & 3);
                float* a4 = acc + (mt * 4 + g) * 4;
                a4[0] = fmaxf(a4[0] + bsp[c0], 0.f);
                a4[1] = fmaxf(a4[1] + bsp[c0 + 1], 0.f);
                a4[2] = fmaxf(a4[2] + bsp[c0], 0.f);
                a4[3] = fmaxf(a4[3] + bsp[c0 + 1], 0.f);
                ss[mt][0] += a4[0] * a4[0] + a4[1] * a4[1];
                ss[mt][1] += a4[2] * a4[2] + a4[3] * a4[3];
            }
#pragma unroll
        for (int mt = 0; mt < 2; mt++)
#pragma unroll
            for (int h = 0; h < 2; h++) {
                float v = ss[mt][h];
                v += __shfl_xor_sync(0xffffffffu, v, 1);
                v += __shfl_xor_sync(0xffffffffu, v, 2);
                ss[mt][h] = v;
            }
        if ((lane & 3) == 0) {
#pragma unroll
            for (int mt = 0; mt < 2; mt++)
#pragma unroll
                for (int h = 0; h < 2; h++) {
                    int rl = mb + mt * 16 + (lane >> 2) + h * 8;
                    ssb[rl * 4 + wn] = ss[mt][h];
                }
        }
        __syncthreads();

#pragma unroll
        for (int mt = 0; mt < 2; mt++)
#pragma unroll
            for (int h = 0; h < 2; h++) {
                int rl = mb + mt * 16 + (lane >> 2) + h * 8;
                int rg = row0 + rl;
                float tsum = ssb[rl * 4] + ssb[rl * 4 + 1] + ssb[rl * 4 + 2] + ssb[rl * 4 + 3];
                float sc = (tsum > 0.f) ? rsqrtf(tsum) : 1.f;
                int ai = 0;
                if (addIdx) {
                    ai = addIdx[rg];
                    if ((lane & 3) == 0 && wn == 0) bias_out[rg] = biasv[ai];
                }
#pragma unroll
                for (int g = 0; g < 4; g++) {
                    int c0 = nb + g * 8 + 2 * (lane & 3);
                    float* a4 = acc + (mt * 4 + g) * 4 + h * 2;
                    float2 o;
                    o.x = a4[0] * sc;
                    o.y = a4[1] * sc;
                    if (addIdx) {
                        float2 av = *(const float2*)(addX + (size_t)ai * 128 + c0);
                        o.x += av.x; o.y += av.y;
                    }
                    *(float2*)(out + (size_t)rg * 128 + c0) = o;
                }
            }
        __syncthreads();
    }
}

// ---------------- pair scores ----------------
__global__ __launch_bounds__(256) void score_kernel(
    const float* __restrict__ h, const float* __restrict__ bn,
    const int* __restrict__ ps, const int* __restrict__ pd,
    const int* __restrict__ ns, const int* __restrict__ nd,
    float* __restrict__ out)
{
    int e = (blockIdx.x * blockDim.x + threadIdx.x) >> 5;
    if (e >= EP) return;
    int lane = threadIdx.x & 31;
    int a = ps[e], b2 = pd[e], c = ns[e], d2 = nd[e];

    float4 u, v;
    u = ((const float4*)(h + (size_t)a * 128))[lane];
    v = ((const float4*)(h + (size_t)b2 * 128))[lane];
    float sp = u.x * v.x + u.y * v.y + u.z * v.z + u.w * v.w;
    u = ((const float4*)(h + (size_t)c * 128))[lane];
    v = ((const float4*)(h + (size_t)d2 * 128))[lane];
    float sn = u.x * v.x + u.y * v.y + u.z * v.z + u.w * v.w;
#pragma unroll
    for (int o = 16; o; o >>= 1) {
        sp += __shfl_xor_sync(0xffffffffu, sp, o);
        sn += __shfl_xor_sync(0xffffffffu, sn, o);
    }
    if (lane == 0) {
        float pos = sp + bn[a] + bn[b2];
        float neg = sn + bn[c] + bn[d2];
        out[e] = fmaxf(neg - pos + 1.0f, 0.f);
    }
}

// ---------------- launch ----------------
extern "C" void kernel_launch(void* const* d_in, const int* in_sizes, int n_in,
                              void* d_out, int out_size)
{
    const float* emb  = (const float*)d_in[0];
    const float* bias = (const float*)d_in[1];
    const int*   nids = (const int*)d_in[2];
    const int*   src0 = (const int*)d_in[3];
    const int*   dst0 = (const int*)d_in[4];
    const float* w0   = (const float*)d_in[5];
    const int*   src1 = (const int*)d_in[6];
    const int*   dst1 = (const int*)d_in[7];
    const float* w1   = (const float*)d_in[8];
    const int*   pos_src = (const int*)d_in[9];
    const int*   pos_dst = (const int*)d_in[10];
    const int*   neg_src = (const int*)d_in[11];
    const int*   neg_dst = (const int*)d_in[12];
    const float* Q0w = (const float*)d_in[13];
    const float* Q0b = (const float*)d_in[14];
    const float* W0w = (const float*)d_in[15];
    const float* W0b = (const float*)d_in[16];
    const float* Q1w = (const float*)d_in[17];
    const float* Q1b = (const float*)d_in[18];
    const float* W1w = (const float*)d_in[19];
    const float* W1b = (const float*)d_in[20];
    float* out = (float*)d_out;

    float *p_m, *p_ws, *p_h1, *p_hi, *p_b;
    uint8_t* p_img;
    cudaGetSymbolAddress((void**)&p_m,  g_m);
    cudaGetSymbolAddress((void**)&p_ws, g_ws);
    cudaGetSymbolAddress((void**)&p_h1, g_h1);
    cudaGetSymbolAddress((void**)&p_hi, g_hitem);
    cudaGetSymbolAddress((void**)&p_b,  g_bias);
    cudaGetSymbolAddress((void**)&p_img, g_wimg);

    const int SMEM_G = 1024 + 16384 + 32768;                // 50176
    const int SMEM_Z = 2560 + 32768 + 65536;                // 100864
    cudaFuncSetAttribute(gemm_scatter, cudaFuncAttributeMaxDynamicSharedMemorySize, SMEM_G);
    cudaFuncSetAttribute(zconv_mma,    cudaFuncAttributeMaxDynamicSharedMemorySize, SMEM_Z);

    prep_weight_all<<<128, 256>>>(Q0w, W0w, Q1w, W1w, p_img);

    const int GS_GRID = 296;
    const int ZC_GRID = 148;

    // layer 0: fused n = relu(emb[nids[src0]] @ Q0 + b0); scatter into m, ws
    zero_kernel<<<(N1 * 32 + 255) / 256, 256>>>((float4*)p_m, N1 * 32);
    zero_kernel<<<(N1 / 4 + 255) / 256, 256>>>((float4*)p_ws, N1 / 4);
    gemm_scatter<<<GS_GRID, 256, SMEM_G>>>(emb, nids, src0, dst0, w0,
                                           p_img + IMG_Q0, Q0b, p_m, p_ws, E0 / 64);

    // h1 = normalize(relu(concat(m/ws, emb[nids]) @ W0 + b0))
    zconv_mma<<<ZC_GRID, 512, SMEM_Z>>>(p_m, p_ws, emb, nids, p_img + IMG_W0, W0b,
                                        nullptr, nullptr, nullptr, nullptr, p_h1,
                                        N1 / 128);

    // layer 1: fused n1 = relu(h1[src1] @ Q1 + b1); scatter into m, ws
    zero_kernel<<<(N2 * 32 + 255) / 256, 256>>>((float4*)p_m, N2 * 32);
    zero_kernel<<<(N2 / 4 + 255) / 256, 256>>>((float4*)p_ws, N2 / 4);
    gemm_scatter<<<GS_GRID, 256, SMEM_G>>>(p_h1, nullptr, src1, dst1, w1,
                                           p_img + IMG_Q1, Q1b, p_m, p_ws, E1 / 64);

    // h_item = emb[nids[:N2]] + normalize(relu(concat(m/ws, h1) @ W1 + b1))
    zconv_mma<<<128, 512, SMEM_Z>>>(p_m, p_ws, p_h1, nullptr, p_img + IMG_W1, W1b,
                                    emb, nids, bias, p_b, p_hi, N2 / 128);

    score_kernel<<<(EP * 32) / 256, 256>>>(p_hi, p_b, pos_src, pos_dst,
                                           neg_src, neg_dst, out);
}